// round 3
// baseline (speedup 1.0000x reference)
#include <cuda_runtime.h>
#include <math.h>

#define Bn     64
#define Tn     1024
#define FRAMEn 512
#define ENCn   256
#define HIDn   512
#define G4n    2048
#define NBLK   128      // persistent LSTM grid size (<= 148 SMs, 1 CTA/SM)

// ---------------- static device scratch (no cudaMalloc allowed) --------------
__device__ float g_encoded[(size_t)Bn * Tn * ENCn];   // 64 MB
__device__ float g_buf[(size_t)Bn * Tn * ENCn];       // 64 MB  enc_norm -> est
__device__ float g_pre[(size_t)Bn * Tn * G4n];        // 512 MB pre1 -> pre2
__device__ float g_x1[(size_t)Bn * Tn * HIDn];        // 128 MB x1 -> x2
__device__ float g_h[2][Bn * HIDn];                   // h ping-pong
__device__ unsigned g_bar_count;                      // grid barrier (self-reset)
__device__ unsigned g_bar_gen;                        // monotonic across replays

// ---------------- software grid barrier (graph-replay safe) ------------------
__device__ __forceinline__ void grid_sync() {
    __syncthreads();
    if (threadIdx.x == 0) {
        __threadfence();
        unsigned gen = ((volatile unsigned*)&g_bar_gen)[0];
        unsigned t = atomicAdd(&g_bar_count, 1u);
        if (t == NBLK - 1) {
            g_bar_count = 0;
            __threadfence();
            atomicAdd(&g_bar_gen, 1u);
        } else {
            while (((volatile unsigned*)&g_bar_gen)[0] == gen) { }
        }
        __threadfence();
    }
    __syncthreads();
}

// =============================================================================
// Generic SIMT fp32 GEMM:  C[M,N] = op(A) @ B^T      (B is [N,K] row-major)
//   TRANS_A==0: A is [M,K] row-major.   TRANS_A==1: A is [K,M] (lda = M).
//   EPI 0: C = acc
//   EPI 1: C = acc + bias1[n] + bias2[n]
//   EPI 2: C = sigmoid(acc + bias1[n]) * E[m,n]
// Tiles 128x128, BK=8, 256 threads, 8x8 per thread. All dims divide evenly.
// =============================================================================
template <int TRANS_A, int EPI>
__global__ void __launch_bounds__(256) gemm_k(
    const float* __restrict__ A, const float* __restrict__ Bm,
    float* __restrict__ C, const float* __restrict__ E,
    const float* __restrict__ bias1, const float* __restrict__ bias2,
    int M, int N, int K, size_t sA, size_t sB, size_t sC)
{
    __shared__ float As[8 * 128];
    __shared__ float Bs[8 * 128];

    const int tid = threadIdx.x;
    const size_t z = blockIdx.z;
    const float* Ab = A + z * sA;
    const float* Bb = Bm + z * sB;
    float*       Cb = C + z * sC;
    const float* Eb = (EPI == 2) ? (E + z * sC) : (const float*)0;

    const int n0 = blockIdx.x * 128;
    const int m0 = blockIdx.y * 128;
    const int tx = tid & 15;          // n-fragment
    const int ty = tid >> 4;          // m-fragment

    const int row  = tid >> 1;        // 0..127 (A/B row loader, non-trans)
    const int half = tid & 1;         // which 4-wide half of K slab
    const int kr   = tid >> 5;        // 0..7   (trans-A loader: k row)
    const int mc   = tid & 31;        // 0..31  (trans-A loader: m quad)

    float acc[8][8];
#pragma unroll
    for (int i = 0; i < 8; i++)
#pragma unroll
        for (int j = 0; j < 8; j++) acc[i][j] = 0.f;

    for (int k0 = 0; k0 < K; k0 += 8) {
        if (TRANS_A) {
            // A[k,m], lda = M
            *(float4*)&As[kr * 128 + mc * 4] =
                *(const float4*)(Ab + (size_t)(k0 + kr) * M + m0 + mc * 4);
        } else {
            float4 va = *(const float4*)(Ab + (size_t)(m0 + row) * K + k0 + half * 4);
            As[(half * 4 + 0) * 128 + row] = va.x;
            As[(half * 4 + 1) * 128 + row] = va.y;
            As[(half * 4 + 2) * 128 + row] = va.z;
            As[(half * 4 + 3) * 128 + row] = va.w;
        }
        {
            float4 vb = *(const float4*)(Bb + (size_t)(n0 + row) * K + k0 + half * 4);
            Bs[(half * 4 + 0) * 128 + row] = vb.x;
            Bs[(half * 4 + 1) * 128 + row] = vb.y;
            Bs[(half * 4 + 2) * 128 + row] = vb.z;
            Bs[(half * 4 + 3) * 128 + row] = vb.w;
        }
        __syncthreads();

#pragma unroll
        for (int kk = 0; kk < 8; kk++) {
            float a[8], bv[8];
            *(float4*)(a)      = *(const float4*)&As[kk * 128 + ty * 8];
            *(float4*)(a + 4)  = *(const float4*)&As[kk * 128 + ty * 8 + 4];
            *(float4*)(bv)     = *(const float4*)&Bs[kk * 128 + tx * 8];
            *(float4*)(bv + 4) = *(const float4*)&Bs[kk * 128 + tx * 8 + 4];
#pragma unroll
            for (int i = 0; i < 8; i++)
#pragma unroll
                for (int j = 0; j < 8; j++) acc[i][j] += a[i] * bv[j];
        }
        __syncthreads();
    }

#pragma unroll
    for (int i = 0; i < 8; i++) {
        const int m = m0 + ty * 8 + i;
        float* crow = Cb + (size_t)m * N;
#pragma unroll
        for (int j = 0; j < 8; j += 4) {
            const int n = n0 + tx * 8 + j;
            float4 v = make_float4(acc[i][j], acc[i][j + 1], acc[i][j + 2], acc[i][j + 3]);
            if (EPI == 1) {
                v.x += bias1[n]     + bias2[n];
                v.y += bias1[n + 1] + bias2[n + 1];
                v.z += bias1[n + 2] + bias2[n + 2];
                v.w += bias1[n + 3] + bias2[n + 3];
            } else if (EPI == 2) {
                float4 e = *(const float4*)(Eb + (size_t)m * N + n);
                v.x = e.x / (1.f + expf(-(v.x + bias1[n])));
                v.y = e.y / (1.f + expf(-(v.y + bias1[n + 1])));
                v.z = e.z / (1.f + expf(-(v.z + bias1[n + 2])));
                v.w = e.w / (1.f + expf(-(v.w + bias1[n + 3])));
            }
            *(float4*)(crow + n) = v;
        }
    }
}

// ---------------- layernorm over last dim (256), one warp per row ------------
__global__ void __launch_bounds__(256) ln_kernel(
    const float* __restrict__ in, float* __restrict__ out,
    const float* __restrict__ gam, const float* __restrict__ bet)
{
    const int rowsPerBlk = 8;
    const int row  = blockIdx.x * rowsPerBlk + (threadIdx.x >> 5);
    const int lane = threadIdx.x & 31;
    const float* r = in + (size_t)row * ENCn + lane * 8;
    float4 a  = *(const float4*)r;
    float4 b4 = *(const float4*)(r + 4);
    float s  = a.x + a.y + a.z + a.w + b4.x + b4.y + b4.z + b4.w;
    float sq = a.x*a.x + a.y*a.y + a.z*a.z + a.w*a.w
             + b4.x*b4.x + b4.y*b4.y + b4.z*b4.z + b4.w*b4.w;
#pragma unroll
    for (int o = 16; o; o >>= 1) {
        s  += __shfl_xor_sync(0xFFFFFFFFu, s,  o);
        sq += __shfl_xor_sync(0xFFFFFFFFu, sq, o);
    }
    const float mu   = s * (1.f / 256.f);
    const float var  = sq * (1.f / 256.f) - mu * mu;
    const float rstd = rsqrtf(var + 1e-5f);

    float* o = out + (size_t)row * ENCn + lane * 8;
    const float* gg = gam + lane * 8;
    const float* bb = bet + lane * 8;
    float4 ga = *(const float4*)gg,      gb = *(const float4*)(gg + 4);
    float4 ba = *(const float4*)bb,      bbv = *(const float4*)(bb + 4);
    float4 o1, o2;
    o1.x = (a.x  - mu) * rstd * ga.x + ba.x;
    o1.y = (a.y  - mu) * rstd * ga.y + ba.y;
    o1.z = (a.z  - mu) * rstd * ga.z + ba.z;
    o1.w = (a.w  - mu) * rstd * ga.w + ba.w;
    o2.x = (b4.x - mu) * rstd * gb.x + bbv.x;
    o2.y = (b4.y - mu) * rstd * gb.y + bbv.y;
    o2.z = (b4.z - mu) * rstd * gb.z + bbv.z;
    o2.w = (b4.w - mu) * rstd * gb.w + bbv.w;
    *(float4*)o       = o1;
    *(float4*)(o + 4) = o2;
}

// ---------------- persistent LSTM layer (grid barrier per step) --------------
// CTA: 16 u-units x 16 batches. Whh slice (4 gates x 16 u x 512) in SMEM.
__global__ void __launch_bounds__(256) lstm_kernel(
    const float* __restrict__ pre, const float* __restrict__ Whh,
    const float* __restrict__ h0,  const float* __restrict__ c0,
    float* __restrict__ xout, float* __restrict__ hout, float* __restrict__ cout)
{
    extern __shared__ float sm[];
    float* sW = sm;                 // 4*16*512 floats
    float* sH = sm + 4 * 16 * 512;  // 16*512 floats

    const int tid = threadIdx.x, cta = blockIdx.x;
    const int ub = cta & 31, bb = cta >> 5;   // 32 u-blocks x 4 b-blocks
    const int ul = tid & 15, bl = tid >> 4;
    const int u = ub * 16 + ul;
    const int b = bb * 16 + bl;

    // load Whh slice: rows {q*512+u'} for q in 0..3, u' in this u-block
    for (int i = tid; i < 64 * 128; i += 256) {
        const int r  = i >> 7;         // 0..63
        const int k4 = i & 127;
        const int q  = r >> 4;
        const int uu = ub * 16 + (r & 15);
        ((float4*)sW)[i] = *(const float4*)(Whh + ((size_t)(q * HIDn + uu)) * HIDn + k4 * 4);
    }
    // init h ping-pong buffer 0 (128*256 threads == 32768 elements exactly)
    g_h[0][cta * 256 + tid] = h0[cta * 256 + tid];
    float c = c0[b * HIDn + u];
    grid_sync();

    const float4* w0 = (const float4*)(sW + (0 * 16 + ul) * HIDn);
    const float4* w1 = (const float4*)(sW + (1 * 16 + ul) * HIDn);
    const float4* w2 = (const float4*)(sW + (2 * 16 + ul) * HIDn);
    const float4* w3 = (const float4*)(sW + (3 * 16 + ul) * HIDn);
    const float4* hv = (const float4*)(sH + bl * HIDn);

    float hnew = 0.f;
    for (int t = 0; t < Tn; t++) {
        const float* hr = g_h[t & 1];
        for (int i = tid; i < 16 * 128; i += 256) {
            const int blx = i >> 7, k4 = i & 127;
            ((float4*)sH)[i] = *(const float4*)(hr + (bb * 16 + blx) * HIDn + k4 * 4);
        }
        __syncthreads();

        float ai = 0.f, af = 0.f, ag = 0.f, ao = 0.f;
#pragma unroll 8
        for (int k = 0; k < 128; k++) {
            const float4 h4 = hv[k];
            float4 w;
            w = w0[k]; ai += w.x*h4.x + w.y*h4.y + w.z*h4.z + w.w*h4.w;
            w = w1[k]; af += w.x*h4.x + w.y*h4.y + w.z*h4.z + w.w*h4.w;
            w = w2[k]; ag += w.x*h4.x + w.y*h4.y + w.z*h4.z + w.w*h4.w;
            w = w3[k]; ao += w.x*h4.x + w.y*h4.y + w.z*h4.z + w.w*h4.w;
        }
        const float* pr = pre + ((size_t)b * Tn + t) * G4n + u;
        const float gi = ai + pr[0];
        const float gf = af + pr[512];
        const float gc = ag + pr[1024];
        const float go = ao + pr[1536];
        const float si = 1.f / (1.f + expf(-gi));
        const float sf = 1.f / (1.f + expf(-gf));
        const float so = 1.f / (1.f + expf(-go));
        c = sf * c + si * tanhf(gc);
        hnew = so * tanhf(c);
        xout[((size_t)b * Tn + t) * HIDn + u] = hnew;
        g_h[(t + 1) & 1][b * HIDn + u] = hnew;
        grid_sync();
    }
    hout[b * HIDn + u] = hnew;
    cout[b * HIDn + u] = c;
}

// =============================================================================
extern "C" void kernel_launch(void* const* d_in, const int* in_sizes, int n_in,
                              void* d_out, int out_size)
{
    const float* x      = (const float*)d_in[0];
    const float* states = (const float*)d_in[1];
    const float* W_enc  = (const float*)d_in[2];
    const float* ln_g   = (const float*)d_in[3];
    const float* ln_b   = (const float*)d_in[4];
    const float* Wih1   = (const float*)d_in[5];
    const float* Whh1   = (const float*)d_in[6];
    const float* bih1   = (const float*)d_in[7];
    const float* bhh1   = (const float*)d_in[8];
    const float* Wih2   = (const float*)d_in[9];
    const float* Whh2   = (const float*)d_in[10];
    const float* bih2   = (const float*)d_in[11];
    const float* bhh2   = (const float*)d_in[12];
    const float* Wlin   = (const float*)d_in[13];
    const float* blin   = (const float*)d_in[14];
    const float* W_dec  = (const float*)d_in[15];

    float* out     = (float*)d_out;
    float* dstates = out + (size_t)Bn * FRAMEn * Tn;   // [4,B,HID]

    float *encoded, *buf, *pre, *x1;
    cudaGetSymbolAddress((void**)&encoded, g_encoded);
    cudaGetSymbolAddress((void**)&buf,     g_buf);
    cudaGetSymbolAddress((void**)&pre,     g_pre);
    cudaGetSymbolAddress((void**)&x1,      g_x1);

    static int smem_set = 0;
    const int LSTM_SMEM = (4 * 16 * 512 + 16 * 512) * 4;   // 163840 B
    if (!smem_set) {
        cudaFuncSetAttribute(lstm_kernel,
                             cudaFuncAttributeMaxDynamicSharedMemorySize, LSTM_SMEM);
        smem_set = 1;
    }

    const int BH = Bn * HIDn;   // 32768

    // 1) encoder: encoded[b,t,o] = sum_c x[b,c,t] * W_enc[o,c]
    //    M=T (trans-A, lda=T), N=ENC, K=FRAME, per-batch z
    gemm_k<1, 0><<<dim3(ENCn / 128, Tn / 128, Bn), 256>>>(
        x, W_enc, encoded, 0, 0, 0,
        Tn, ENCn, FRAMEn, (size_t)FRAMEn * Tn, 0, (size_t)Tn * ENCn);

    // 2) layernorm -> enc_norm in g_buf
    ln_kernel<<<(Bn * Tn) / 8, 256>>>(encoded, buf, ln_g, ln_b);

    // 3) pre1 = enc_norm @ Wih1^T + bih1 + bhh1   [65536, 2048]
    gemm_k<0, 1><<<dim3(G4n / 128, (Bn * Tn) / 128, 1), 256>>>(
        buf, Wih1, pre, 0, bih1, bhh1,
        Bn * Tn, G4n, ENCn, 0, 0, 0);

    // 4) LSTM layer 1: x1, h1, c1
    lstm_kernel<<<NBLK, 256, LSTM_SMEM>>>(
        pre, Whh1, states + 0 * BH, states + 1 * BH,
        x1, dstates + 0 * BH, dstates + 1 * BH);

    // 5) pre2 = x1 @ Wih2^T + bih2 + bhh2
    gemm_k<0, 1><<<dim3(G4n / 128, (Bn * Tn) / 128, 1), 256>>>(
        x1, Wih2, pre, 0, bih2, bhh2,
        Bn * Tn, G4n, HIDn, 0, 0, 0);

    // 6) LSTM layer 2: x2 (reuse g_x1), h2, c2
    lstm_kernel<<<NBLK, 256, LSTM_SMEM>>>(
        pre, Whh2, states + 2 * BH, states + 3 * BH,
        x1, dstates + 2 * BH, dstates + 3 * BH);

    // 7) est = sigmoid(x2 @ Wlin^T + blin) * encoded   -> g_buf
    gemm_k<0, 2><<<dim3(ENCn / 128, (Bn * Tn) / 128, 1), 256>>>(
        x1, Wlin, buf, encoded, blin, 0,
        Bn * Tn, ENCn, HIDn, 0, 0, 0);

    // 8) decoder: decoded[b,f,t] = sum_o W_dec[f,o] * est[b,t,o]
    //    M=FRAME, N=T, K=ENC, A=W_dec (shared), B=est_b [T,ENC]
    gemm_k<0, 0><<<dim3(Tn / 128, FRAMEn / 128, Bn), 256>>>(
        W_dec, buf, out, 0, 0, 0,
        FRAMEn, Tn, ENCn, 0, (size_t)Tn * ENCn, (size_t)FRAMEn * Tn);
}

// round 4
// speedup vs baseline: 4.6302x; 4.6302x over previous
#include <cuda_runtime.h>
#include <math.h>

#define Bn     64
#define Tn     1024
#define FRAMEn 512
#define ENCn   256
#define HIDn   512
#define G4n    2048
#define NBLK   128      // persistent LSTM grid (1 CTA/SM, co-resident)
#define GSIZE  32       // CTAs per barrier group (one batch-block)
#define WROW   516      // padded SMEM row stride (floats): 129*16B -> conflict-free

// ---------------- static device scratch (no cudaMalloc allowed) --------------
__device__ float g_encoded[(size_t)Bn * Tn * ENCn];   // 64 MB
__device__ float g_buf[(size_t)Bn * Tn * ENCn];       // 64 MB  enc_norm -> est
__device__ float g_pre[(size_t)Bn * Tn * G4n];        // 512 MB pre1 -> pre2
__device__ float g_x1[(size_t)Bn * Tn * HIDn];        // 128 MB x1 -> x2
__device__ float g_h[2][Bn * HIDn];                   // h ping-pong
__device__ unsigned g_cnt[4];                         // per-group barrier count
__device__ unsigned g_gen[4];                         // per-group generation

// ---------------- per-group software barrier (graph-replay safe) -------------
__device__ __forceinline__ void group_sync(int g) {
    __syncthreads();
    if (threadIdx.x == 0) {
        __threadfence();
        unsigned gen = ((volatile unsigned*)g_gen)[g];
        if (atomicAdd(&g_cnt[g], 1u) == GSIZE - 1) {
            g_cnt[g] = 0;
            __threadfence();
            atomicAdd(&g_gen[g], 1u);
        } else {
            while (((volatile unsigned*)g_gen)[g] == gen) { }
        }
        __threadfence();
    }
    __syncthreads();
}

// packed f32x2 FMA: d = a*b + d (elementwise on 2 packed floats)
__device__ __forceinline__ void fma2(unsigned long long& d,
                                     unsigned long long a, unsigned long long b) {
    asm("fma.rn.f32x2 %0, %1, %2, %0;" : "+l"(d) : "l"(a), "l"(b));
}
__device__ __forceinline__ float psum(unsigned long long v) {
    return __uint_as_float((unsigned)v) + __uint_as_float((unsigned)(v >> 32));
}

// =============================================================================
// Generic SIMT fp32 GEMM:  C[M,N] = op(A) @ B^T      (B is [N,K] row-major)
//   TRANS_A==0: A is [M,K] row-major.   TRANS_A==1: A is [K,M] (lda = M).
//   EPI 0: C = acc
//   EPI 1: C = acc + bias1[n] + bias2[n]
//   EPI 2: C = sigmoid(acc + bias1[n]) * E[m,n]
// Tiles 128x128, BK=8, 256 threads, 8x8 per thread. All dims divide evenly.
// =============================================================================
template <int TRANS_A, int EPI>
__global__ void __launch_bounds__(256) gemm_k(
    const float* __restrict__ A, const float* __restrict__ Bm,
    float* __restrict__ C, const float* __restrict__ E,
    const float* __restrict__ bias1, const float* __restrict__ bias2,
    int M, int N, int K, size_t sA, size_t sB, size_t sC)
{
    __shared__ float As[8 * 128];
    __shared__ float Bs[8 * 128];

    const int tid = threadIdx.x;
    const size_t z = blockIdx.z;
    const float* Ab = A + z * sA;
    const float* Bb = Bm + z * sB;
    float*       Cb = C + z * sC;
    const float* Eb = (EPI == 2) ? (E + z * sC) : (const float*)0;

    const int n0 = blockIdx.x * 128;
    const int m0 = blockIdx.y * 128;
    const int tx = tid & 15;
    const int ty = tid >> 4;

    const int row  = tid >> 1;
    const int half = tid & 1;
    const int kr   = tid >> 5;
    const int mc   = tid & 31;

    float acc[8][8];
#pragma unroll
    for (int i = 0; i < 8; i++)
#pragma unroll
        for (int j = 0; j < 8; j++) acc[i][j] = 0.f;

    for (int k0 = 0; k0 < K; k0 += 8) {
        if (TRANS_A) {
            *(float4*)&As[kr * 128 + mc * 4] =
                *(const float4*)(Ab + (size_t)(k0 + kr) * M + m0 + mc * 4);
        } else {
            float4 va = *(const float4*)(Ab + (size_t)(m0 + row) * K + k0 + half * 4);
            As[(half * 4 + 0) * 128 + row] = va.x;
            As[(half * 4 + 1) * 128 + row] = va.y;
            As[(half * 4 + 2) * 128 + row] = va.z;
            As[(half * 4 + 3) * 128 + row] = va.w;
        }
        {
            float4 vb = *(const float4*)(Bb + (size_t)(n0 + row) * K + k0 + half * 4);
            Bs[(half * 4 + 0) * 128 + row] = vb.x;
            Bs[(half * 4 + 1) * 128 + row] = vb.y;
            Bs[(half * 4 + 2) * 128 + row] = vb.z;
            Bs[(half * 4 + 3) * 128 + row] = vb.w;
        }
        __syncthreads();

#pragma unroll
        for (int kk = 0; kk < 8; kk++) {
            float a[8], bv[8];
            *(float4*)(a)      = *(const float4*)&As[kk * 128 + ty * 8];
            *(float4*)(a + 4)  = *(const float4*)&As[kk * 128 + ty * 8 + 4];
            *(float4*)(bv)     = *(const float4*)&Bs[kk * 128 + tx * 8];
            *(float4*)(bv + 4) = *(const float4*)&Bs[kk * 128 + tx * 8 + 4];
#pragma unroll
            for (int i = 0; i < 8; i++)
#pragma unroll
                for (int j = 0; j < 8; j++) acc[i][j] += a[i] * bv[j];
        }
        __syncthreads();
    }

#pragma unroll
    for (int i = 0; i < 8; i++) {
        const int m = m0 + ty * 8 + i;
        float* crow = Cb + (size_t)m * N;
#pragma unroll
        for (int j = 0; j < 8; j += 4) {
            const int n = n0 + tx * 8 + j;
            float4 v = make_float4(acc[i][j], acc[i][j + 1], acc[i][j + 2], acc[i][j + 3]);
            if (EPI == 1) {
                v.x += bias1[n]     + bias2[n];
                v.y += bias1[n + 1] + bias2[n + 1];
                v.z += bias1[n + 2] + bias2[n + 2];
                v.w += bias1[n + 3] + bias2[n + 3];
            } else if (EPI == 2) {
                float4 e = *(const float4*)(Eb + (size_t)m * N + n);
                v.x = e.x / (1.f + expf(-(v.x + bias1[n])));
                v.y = e.y / (1.f + expf(-(v.y + bias1[n + 1])));
                v.z = e.z / (1.f + expf(-(v.z + bias1[n + 2])));
                v.w = e.w / (1.f + expf(-(v.w + bias1[n + 3])));
            }
            *(float4*)(crow + n) = v;
        }
    }
}

// ---------------- layernorm over last dim (256), one warp per row ------------
__global__ void __launch_bounds__(256) ln_kernel(
    const float* __restrict__ in, float* __restrict__ out,
    const float* __restrict__ gam, const float* __restrict__ bet)
{
    const int row  = blockIdx.x * 8 + (threadIdx.x >> 5);
    const int lane = threadIdx.x & 31;
    const float* r = in + (size_t)row * ENCn + lane * 8;
    float4 a  = *(const float4*)r;
    float4 b4 = *(const float4*)(r + 4);
    float s  = a.x + a.y + a.z + a.w + b4.x + b4.y + b4.z + b4.w;
    float sq = a.x*a.x + a.y*a.y + a.z*a.z + a.w*a.w
             + b4.x*b4.x + b4.y*b4.y + b4.z*b4.z + b4.w*b4.w;
#pragma unroll
    for (int o = 16; o; o >>= 1) {
        s  += __shfl_xor_sync(0xFFFFFFFFu, s,  o);
        sq += __shfl_xor_sync(0xFFFFFFFFu, sq, o);
    }
    const float mu   = s * (1.f / 256.f);
    const float var  = sq * (1.f / 256.f) - mu * mu;
    const float rstd = rsqrtf(var + 1e-5f);

    float* o = out + (size_t)row * ENCn + lane * 8;
    const float* gg = gam + lane * 8;
    const float* bb = bet + lane * 8;
    float4 ga = *(const float4*)gg,  gb  = *(const float4*)(gg + 4);
    float4 ba = *(const float4*)bb,  bbv = *(const float4*)(bb + 4);
    float4 o1, o2;
    o1.x = (a.x  - mu) * rstd * ga.x + ba.x;
    o1.y = (a.y  - mu) * rstd * ga.y + ba.y;
    o1.z = (a.z  - mu) * rstd * ga.z + ba.z;
    o1.w = (a.w  - mu) * rstd * ga.w + ba.w;
    o2.x = (b4.x - mu) * rstd * gb.x + bbv.x;
    o2.y = (b4.y - mu) * rstd * gb.y + bbv.y;
    o2.z = (b4.z - mu) * rstd * gb.z + bbv.z;
    o2.w = (b4.w - mu) * rstd * gb.w + bbv.w;
    *(float4*)o       = o1;
    *(float4*)(o + 4) = o2;
}

// ---------------- persistent LSTM layer (per-group barrier per step) ---------
// Grid: 128 CTAs = 32 u-blocks (16 units) x 4 b-blocks (16 batches).
// Warp tiling: 4 units x 8 batches per warp -> w rows broadcast to 8 lanes,
// 4 unique 16B rows per LDS.128 (1 crossbar phase with WROW padding).
__global__ void __launch_bounds__(256) lstm_kernel(
    const float* __restrict__ pre, const float* __restrict__ Whh,
    const float* __restrict__ h0,  const float* __restrict__ c0,
    float* __restrict__ xout, float* __restrict__ hout, float* __restrict__ cout)
{
    extern __shared__ float sm[];
    float* sW = sm;                 // 64 rows x WROW
    float* sH = sm + 64 * WROW;     // 16 rows x WROW

    const int tid  = threadIdx.x, cta = blockIdx.x;
    const int ub   = cta & 31, bb = cta >> 5;
    const int warp = tid >> 5, lane = tid & 31;
    const int ul = (warp & 3) * 4 + (lane & 3);     // 0..15
    const int bl = (warp >> 2) * 8 + (lane >> 2);   // 0..15
    const int u = ub * 16 + ul;
    const int b = bb * 16 + bl;

    // load Whh slice: rows {q*512 + (ub*16+r)} into padded SMEM
    for (int i = tid; i < 64 * 128; i += 256) {
        const int r  = i >> 7;          // 0..63  (= q*16 + ulocal)
        const int k4 = i & 127;
        const int q  = r >> 4;
        const int uu = ub * 16 + (r & 15);
        *(float4*)(sW + r * WROW + k4 * 4) =
            *(const float4*)(Whh + ((size_t)(q * HIDn + uu)) * HIDn + k4 * 4);
    }
    // init h ping-pong buffer 0; CTA cta writes exactly the rows its own
    // barrier-group reads (group bb <-> elements [bb*8192, bb*8192+8192))
    g_h[0][cta * 256 + tid] = h0[cta * 256 + tid];
    float c = c0[b * HIDn + u];
    group_sync(bb);

    const ulonglong2* w0 = (const ulonglong2*)(sW + (0 * 16 + ul) * WROW);
    const ulonglong2* w1 = (const ulonglong2*)(sW + (1 * 16 + ul) * WROW);
    const ulonglong2* w2 = (const ulonglong2*)(sW + (2 * 16 + ul) * WROW);
    const ulonglong2* w3 = (const ulonglong2*)(sW + (3 * 16 + ul) * WROW);
    const ulonglong2* hp = (const ulonglong2*)(sH + bl * WROW);

    float hnew = 0.f;
    for (int t = 0; t < Tn; t++) {
        const float* hr = g_h[t & 1];
        for (int i = tid; i < 16 * 128; i += 256) {
            const int rr = i >> 7, k4 = i & 127;
            *(float4*)(sH + rr * WROW + k4 * 4) =
                *(const float4*)(hr + (bb * 16 + rr) * HIDn + k4 * 4);
        }
        const float* pr = pre + ((size_t)b * Tn + t) * G4n + u;
        const float pi = pr[0], pf = pr[512], pg = pr[1024], po = pr[1536];
        __syncthreads();

        unsigned long long i0 = 0, i1 = 0, f0 = 0, f1 = 0,
                           g0 = 0, g1 = 0, o0 = 0, o1 = 0;
#pragma unroll 4
        for (int k = 0; k < 128; k++) {
            const ulonglong2 h2 = hp[k];
            ulonglong2 w;
            w = w0[k]; fma2(i0, w.x, h2.x); fma2(i1, w.y, h2.y);
            w = w1[k]; fma2(f0, w.x, h2.x); fma2(f1, w.y, h2.y);
            w = w2[k]; fma2(g0, w.x, h2.x); fma2(g1, w.y, h2.y);
            w = w3[k]; fma2(o0, w.x, h2.x); fma2(o1, w.y, h2.y);
        }
        const float gi = pi + psum(i0) + psum(i1);
        const float gf = pf + psum(f0) + psum(f1);
        const float gc = pg + psum(g0) + psum(g1);
        const float go = po + psum(o0) + psum(o1);
        const float si = 1.f / (1.f + expf(-gi));
        const float sf = 1.f / (1.f + expf(-gf));
        const float so = 1.f / (1.f + expf(-go));
        c = sf * c + si * tanhf(gc);
        hnew = so * tanhf(c);
        xout[((size_t)b * Tn + t) * HIDn + u] = hnew;
        g_h[(t + 1) & 1][b * HIDn + u] = hnew;
        group_sync(bb);
    }
    hout[b * HIDn + u] = hnew;
    cout[b * HIDn + u] = c;
}

// =============================================================================
extern "C" void kernel_launch(void* const* d_in, const int* in_sizes, int n_in,
                              void* d_out, int out_size)
{
    const float* x      = (const float*)d_in[0];
    const float* states = (const float*)d_in[1];
    const float* W_enc  = (const float*)d_in[2];
    const float* ln_g   = (const float*)d_in[3];
    const float* ln_b   = (const float*)d_in[4];
    const float* Wih1   = (const float*)d_in[5];
    const float* Whh1   = (const float*)d_in[6];
    const float* bih1   = (const float*)d_in[7];
    const float* bhh1   = (const float*)d_in[8];
    const float* Wih2   = (const float*)d_in[9];
    const float* Whh2   = (const float*)d_in[10];
    const float* bih2   = (const float*)d_in[11];
    const float* bhh2   = (const float*)d_in[12];
    const float* Wlin   = (const float*)d_in[13];
    const float* blin   = (const float*)d_in[14];
    const float* W_dec  = (const float*)d_in[15];

    float* out     = (float*)d_out;
    float* dstates = out + (size_t)Bn * FRAMEn * Tn;   // [4,B,HID]

    float *encoded, *buf, *pre, *x1;
    cudaGetSymbolAddress((void**)&encoded, g_encoded);
    cudaGetSymbolAddress((void**)&buf,     g_buf);
    cudaGetSymbolAddress((void**)&pre,     g_pre);
    cudaGetSymbolAddress((void**)&x1,      g_x1);

    static int smem_set = 0;
    const int LSTM_SMEM = (64 * WROW + 16 * WROW) * 4;   // 165,120 B
    if (!smem_set) {
        cudaFuncSetAttribute(lstm_kernel,
                             cudaFuncAttributeMaxDynamicSharedMemorySize, LSTM_SMEM);
        smem_set = 1;
    }

    const int BH = Bn * HIDn;   // 32768

    // 1) encoder: encoded[b,t,o] = sum_c x[b,c,t] * W_enc[o,c]
    gemm_k<1, 0><<<dim3(ENCn / 128, Tn / 128, Bn), 256>>>(
        x, W_enc, encoded, 0, 0, 0,
        Tn, ENCn, FRAMEn, (size_t)FRAMEn * Tn, 0, (size_t)Tn * ENCn);

    // 2) layernorm -> enc_norm in g_buf
    ln_kernel<<<(Bn * Tn) / 8, 256>>>(encoded, buf, ln_g, ln_b);

    // 3) pre1 = enc_norm @ Wih1^T + bih1 + bhh1
    gemm_k<0, 1><<<dim3(G4n / 128, (Bn * Tn) / 128, 1), 256>>>(
        buf, Wih1, pre, 0, bih1, bhh1,
        Bn * Tn, G4n, ENCn, 0, 0, 0);

    // 4) LSTM layer 1
    lstm_kernel<<<NBLK, 256, LSTM_SMEM>>>(
        pre, Whh1, states + 0 * BH, states + 1 * BH,
        x1, dstates + 0 * BH, dstates + 1 * BH);

    // 5) pre2 = x1 @ Wih2^T + bih2 + bhh2
    gemm_k<0, 1><<<dim3(G4n / 128, (Bn * Tn) / 128, 1), 256>>>(
        x1, Wih2, pre, 0, bih2, bhh2,
        Bn * Tn, G4n, HIDn, 0, 0, 0);

    // 6) LSTM layer 2 (x2 reuses g_x1)
    lstm_kernel<<<NBLK, 256, LSTM_SMEM>>>(
        pre, Whh2, states + 2 * BH, states + 3 * BH,
        x1, dstates + 2 * BH, dstates + 3 * BH);

    // 7) est = sigmoid(x2 @ Wlin^T + blin) * encoded -> g_buf
    gemm_k<0, 2><<<dim3(ENCn / 128, (Bn * Tn) / 128, 1), 256>>>(
        x1, Wlin, buf, encoded, blin, 0,
        Bn * Tn, ENCn, HIDn, 0, 0, 0);

    // 8) decoder: decoded[b,f,t] = sum_o W_dec[f,o] * est[b,t,o]
    gemm_k<0, 0><<<dim3(Tn / 128, FRAMEn / 128, Bn), 256>>>(
        W_dec, buf, out, 0, 0, 0,
        FRAMEn, Tn, ENCn, 0, (size_t)Tn * ENCn, (size_t)FRAMEn * Tn);
}

// round 5
// speedup vs baseline: 7.5626x; 1.6333x over previous
#include <cuda_runtime.h>
#include <math.h>

#define Bn     64
#define Tn     1024
#define FRAMEn 512
#define ENCn   256
#define HIDn   512
#define G4n    2048
#define NBLK   128      // persistent LSTM grid (1 CTA/SM, co-resident)
#define GSIZE  32       // CTAs per barrier group (one batch-block)
#define WROW   516      // padded SMEM row stride (floats): stride%32 words==4 -> 2-phase LDS
#define RSTR   20       // reduction slot stride (floats): 4-phase STS.128 (minimum)

// ---------------- static device scratch (no cudaMalloc allowed) --------------
__device__ float g_encoded[(size_t)Bn * Tn * ENCn];   // 64 MB
__device__ float g_buf[(size_t)Bn * Tn * ENCn];       // 64 MB  enc_norm -> est
__device__ float g_pre[(size_t)Bn * Tn * G4n];        // 512 MB pre1 -> pre2
__device__ float g_x1[(size_t)Bn * Tn * HIDn];        // 128 MB x1 -> x2
__device__ float g_h[2][Bn * HIDn];                   // h ping-pong
__device__ unsigned g_cnt[4];                         // per-group barrier count
__device__ unsigned g_gen[4];                         // per-group generation

// ---------------- per-group software barrier (graph-replay safe) -------------
__device__ __forceinline__ void group_sync(int g) {
    __syncthreads();
    if (threadIdx.x == 0) {
        __threadfence();
        unsigned gen = ((volatile unsigned*)g_gen)[g];
        if (atomicAdd(&g_cnt[g], 1u) == GSIZE - 1) {
            g_cnt[g] = 0;
            __threadfence();
            atomicAdd(&g_gen[g], 1u);
        } else {
            while (((volatile unsigned*)g_gen)[g] == gen) { }
        }
        __threadfence();
    }
    __syncthreads();
}

// packed f32x2 FMA: d = a*b + d (elementwise on 2 packed floats)
__device__ __forceinline__ void fma2(unsigned long long& d,
                                     unsigned long long a, unsigned long long b) {
    asm("fma.rn.f32x2 %0, %1, %2, %0;" : "+l"(d) : "l"(a), "l"(b));
}
__device__ __forceinline__ float psum(unsigned long long v) {
    return __uint_as_float((unsigned)v) + __uint_as_float((unsigned)(v >> 32));
}

// =============================================================================
// Generic SIMT fp32 GEMM:  C[M,N] = op(A) @ B^T      (B is [N,K] row-major)
//   TRANS_A==0: A is [M,K] row-major.   TRANS_A==1: A is [K,M] (lda = M).
//   EPI 0: C = acc   EPI 1: C = acc + bias1[n] + bias2[n]
//   EPI 2: C = sigmoid(acc + bias1[n]) * E[m,n]
// Tiles 128x128, BK=8, 256 threads, 8x8/thread, register double-buffering.
// =============================================================================
template <int TRANS_A, int EPI>
__global__ void __launch_bounds__(256) gemm_k(
    const float* __restrict__ A, const float* __restrict__ Bm,
    float* __restrict__ C, const float* __restrict__ E,
    const float* __restrict__ bias1, const float* __restrict__ bias2,
    int M, int N, int K, size_t sA, size_t sB, size_t sC)
{
    __shared__ float As[8 * 128];
    __shared__ float Bs[8 * 128];

    const int tid = threadIdx.x;
    const size_t z = blockIdx.z;
    const float* Ab = A + z * sA;
    const float* Bb = Bm + z * sB;
    float*       Cb = C + z * sC;
    const float* Eb = (EPI == 2) ? (E + z * sC) : (const float*)0;

    const int n0 = blockIdx.x * 128;
    const int m0 = blockIdx.y * 128;
    const int tx = tid & 15;
    const int ty = tid >> 4;

    const int row  = tid >> 1;
    const int half = tid & 1;
    const int kr   = tid >> 5;
    const int mc   = tid & 31;

    float acc[8][8];
#pragma unroll
    for (int i = 0; i < 8; i++)
#pragma unroll
        for (int j = 0; j < 8; j++) acc[i][j] = 0.f;

    // prologue prefetch of slab 0
    float4 pa, pb;
    if (TRANS_A) pa = *(const float4*)(Ab + (size_t)kr * M + m0 + mc * 4);
    else         pa = *(const float4*)(Ab + (size_t)(m0 + row) * K + half * 4);
    pb = *(const float4*)(Bb + (size_t)(n0 + row) * K + half * 4);

    for (int k0 = 0; k0 < K; k0 += 8) {
        if (TRANS_A) {
            *(float4*)&As[kr * 128 + mc * 4] = pa;
        } else {
            As[(half * 4 + 0) * 128 + row] = pa.x;
            As[(half * 4 + 1) * 128 + row] = pa.y;
            As[(half * 4 + 2) * 128 + row] = pa.z;
            As[(half * 4 + 3) * 128 + row] = pa.w;
        }
        Bs[(half * 4 + 0) * 128 + row] = pb.x;
        Bs[(half * 4 + 1) * 128 + row] = pb.y;
        Bs[(half * 4 + 2) * 128 + row] = pb.z;
        Bs[(half * 4 + 3) * 128 + row] = pb.w;
        __syncthreads();

        if (k0 + 8 < K) {   // prefetch next slab into registers (hidden by math)
            if (TRANS_A) pa = *(const float4*)(Ab + (size_t)(k0 + 8 + kr) * M + m0 + mc * 4);
            else         pa = *(const float4*)(Ab + (size_t)(m0 + row) * K + k0 + 8 + half * 4);
            pb = *(const float4*)(Bb + (size_t)(n0 + row) * K + k0 + 8 + half * 4);
        }

#pragma unroll
        for (int kk = 0; kk < 8; kk++) {
            float a[8], bv[8];
            *(float4*)(a)      = *(const float4*)&As[kk * 128 + ty * 8];
            *(float4*)(a + 4)  = *(const float4*)&As[kk * 128 + ty * 8 + 4];
            *(float4*)(bv)     = *(const float4*)&Bs[kk * 128 + tx * 8];
            *(float4*)(bv + 4) = *(const float4*)&Bs[kk * 128 + tx * 8 + 4];
#pragma unroll
            for (int i = 0; i < 8; i++)
#pragma unroll
                for (int j = 0; j < 8; j++) acc[i][j] += a[i] * bv[j];
        }
        __syncthreads();
    }

#pragma unroll
    for (int i = 0; i < 8; i++) {
        const int m = m0 + ty * 8 + i;
        float* crow = Cb + (size_t)m * N;
#pragma unroll
        for (int j = 0; j < 8; j += 4) {
            const int n = n0 + tx * 8 + j;
            float4 v = make_float4(acc[i][j], acc[i][j + 1], acc[i][j + 2], acc[i][j + 3]);
            if (EPI == 1) {
                v.x += bias1[n]     + bias2[n];
                v.y += bias1[n + 1] + bias2[n + 1];
                v.z += bias1[n + 2] + bias2[n + 2];
                v.w += bias1[n + 3] + bias2[n + 3];
            } else if (EPI == 2) {
                float4 e = *(const float4*)(Eb + (size_t)m * N + n);
                v.x = e.x / (1.f + expf(-(v.x + bias1[n])));
                v.y = e.y / (1.f + expf(-(v.y + bias1[n + 1])));
                v.z = e.z / (1.f + expf(-(v.z + bias1[n + 2])));
                v.w = e.w / (1.f + expf(-(v.w + bias1[n + 3])));
            }
            *(float4*)(crow + n) = v;
        }
    }
}

// ---------------- layernorm over last dim (256), one warp per row ------------
__global__ void __launch_bounds__(256) ln_kernel(
    const float* __restrict__ in, float* __restrict__ out,
    const float* __restrict__ gam, const float* __restrict__ bet)
{
    const int row  = blockIdx.x * 8 + (threadIdx.x >> 5);
    const int lane = threadIdx.x & 31;
    const float* r = in + (size_t)row * ENCn + lane * 8;
    float4 a  = *(const float4*)r;
    float4 b4 = *(const float4*)(r + 4);
    float s  = a.x + a.y + a.z + a.w + b4.x + b4.y + b4.z + b4.w;
    float sq = a.x*a.x + a.y*a.y + a.z*a.z + a.w*a.w
             + b4.x*b4.x + b4.y*b4.y + b4.z*b4.z + b4.w*b4.w;
#pragma unroll
    for (int o = 16; o; o >>= 1) {
        s  += __shfl_xor_sync(0xFFFFFFFFu, s,  o);
        sq += __shfl_xor_sync(0xFFFFFFFFu, sq, o);
    }
    const float mu   = s * (1.f / 256.f);
    const float var  = sq * (1.f / 256.f) - mu * mu;
    const float rstd = rsqrtf(var + 1e-5f);

    float* o = out + (size_t)row * ENCn + lane * 8;
    const float* gg = gam + lane * 8;
    const float* bb = bet + lane * 8;
    float4 ga = *(const float4*)gg,  gb  = *(const float4*)(gg + 4);
    float4 ba = *(const float4*)bb,  bbv = *(const float4*)(bb + 4);
    float4 o1, o2;
    o1.x = (a.x  - mu) * rstd * ga.x + ba.x;
    o1.y = (a.y  - mu) * rstd * ga.y + ba.y;
    o1.z = (a.z  - mu) * rstd * ga.z + ba.z;
    o1.w = (a.w  - mu) * rstd * ga.w + ba.w;
    o2.x = (b4.x - mu) * rstd * gb.x + bbv.x;
    o2.y = (b4.y - mu) * rstd * gb.y + bbv.y;
    o2.z = (b4.z - mu) * rstd * gb.z + bbv.z;
    o2.w = (b4.w - mu) * rstd * gb.w + bbv.w;
    *(float4*)o       = o1;
    *(float4*)(o + 4) = o2;
}

// ---------------- persistent LSTM layer, v3 ----------------------------------
// Grid: 128 CTAs = 32 u-blocks (16 units) x 4 b-blocks (16 batches).
// Thread = (unit ul, k-quarter ks, 4 batches). Per 4-k quad: 4 w-LDS + 4 h-LDS
// feed 4g x 4b x 4k = 64 FMA (32 fma2). Cross-warp k-reduction via padded SMEM;
// owner warps 0 (bq_hi=0) and 5 (bq_hi=1) run the gate epilogue.
__global__ void __launch_bounds__(256) lstm_kernel(
    const float* __restrict__ pre, const float* __restrict__ Whh,
    const float* __restrict__ h0,  const float* __restrict__ c0,
    float* __restrict__ xout, float* __restrict__ hout, float* __restrict__ cout)
{
    extern __shared__ float sm[];
    float* sW = sm;                    // 64 rows x WROW
    float* sH = sm + 64 * WROW;        // 16 rows x WROW
    float* sR = sm + 80 * WROW;        // 4*64 slots x RSTR

    const int tid  = threadIdx.x, cta = blockIdx.x;
    const int ub   = cta & 31, bb = cta >> 5;
    const int warp = tid >> 5, lane = tid & 31;
    const int ks    = warp & 3;          // k-quarter
    const int bq_hi = warp >> 2;         // 0..1
    const int ul    = lane & 15;
    const int bq_lo = lane >> 4;         // 0..1
    const int bq    = bq_hi * 2 + bq_lo; // 0..3  -> batches bq*4..bq*4+3
    const int u     = ub * 16 + ul;
    const int bbase = bb * 16 + bq * 4;
    const int slot  = bq * 16 + ul;      // 0..63
    const bool owner = (ks == bq_hi);    // warps 0 and 5 (SMSP 0 / SMSP 1)

    // load Whh slice: rows {g*512 + (ub*16+r)} into padded SMEM
    for (int i = tid; i < 64 * 128; i += 256) {
        const int r  = i >> 7;
        const int k4 = i & 127;
        const int g  = r >> 4;
        const int uu = ub * 16 + (r & 15);
        *(float4*)(sW + r * WROW + k4 * 4) =
            *(const float4*)(Whh + ((size_t)(g * HIDn + uu)) * HIDn + k4 * 4);
    }
    g_h[0][cta * 256 + tid] = h0[cta * 256 + tid];
    float c[4];
    if (owner) {
#pragma unroll
        for (int j = 0; j < 4; j++) c[j] = c0[(bbase + j) * HIDn + u];
    }
    group_sync(bb);

    const float* w0r = sW + (0 * 16 + ul) * WROW + ks * 128;
    const float* w1r = sW + (1 * 16 + ul) * WROW + ks * 128;
    const float* w2r = sW + (2 * 16 + ul) * WROW + ks * 128;
    const float* w3r = sW + (3 * 16 + ul) * WROW + ks * 128;
    const float* hb0 = sH + (bq * 4 + 0) * WROW + ks * 128;
    const float* hb1 = sH + (bq * 4 + 1) * WROW + ks * 128;
    const float* hb2 = sH + (bq * 4 + 2) * WROW + ks * 128;
    const float* hb3 = sH + (bq * 4 + 3) * WROW + ks * 128;

    for (int t = 0; t < Tn; t++) {
        // cooperative h -> SMEM
        const float* hr = g_h[t & 1] + (size_t)bb * 16 * HIDn;
        for (int i = tid; i < 16 * 128; i += 256) {
            const int rr = i >> 7, k4 = i & 127;
            *(float4*)(sH + rr * WROW + k4 * 4) =
                *(const float4*)(hr + (size_t)rr * HIDn + k4 * 4);
        }
        // owners: load pre (consumed ~2us later at epilogue -> latency hidden)
        float prg[16];
        if (owner) {
            const float* pb = pre + ((size_t)bbase * Tn + t) * G4n + u;
#pragma unroll
            for (int j = 0; j < 4; j++)
#pragma unroll
                for (int g = 0; g < 4; g++)
                    prg[g * 4 + j] = pb[(size_t)j * Tn * G4n + g * 512];
        }
        __syncthreads();

        unsigned long long acc[16];
#pragma unroll
        for (int i = 0; i < 16; i++) acc[i] = 0ull;

#pragma unroll 4
        for (int q = 0; q < 32; q++) {
            const int k = q * 4;
            const ulonglong2 ha = *(const ulonglong2*)(hb0 + k);
            const ulonglong2 hbv = *(const ulonglong2*)(hb1 + k);
            const ulonglong2 hc = *(const ulonglong2*)(hb2 + k);
            const ulonglong2 hd = *(const ulonglong2*)(hb3 + k);
            ulonglong2 w;
            w = *(const ulonglong2*)(w0r + k);
            fma2(acc[0], w.x, ha.x);  fma2(acc[0], w.y, ha.y);
            fma2(acc[1], w.x, hbv.x); fma2(acc[1], w.y, hbv.y);
            fma2(acc[2], w.x, hc.x);  fma2(acc[2], w.y, hc.y);
            fma2(acc[3], w.x, hd.x);  fma2(acc[3], w.y, hd.y);
            w = *(const ulonglong2*)(w1r + k);
            fma2(acc[4], w.x, ha.x);  fma2(acc[4], w.y, ha.y);
            fma2(acc[5], w.x, hbv.x); fma2(acc[5], w.y, hbv.y);
            fma2(acc[6], w.x, hc.x);  fma2(acc[6], w.y, hc.y);
            fma2(acc[7], w.x, hd.x);  fma2(acc[7], w.y, hd.y);
            w = *(const ulonglong2*)(w2r + k);
            fma2(acc[8], w.x, ha.x);  fma2(acc[8], w.y, ha.y);
            fma2(acc[9], w.x, hbv.x); fma2(acc[9], w.y, hbv.y);
            fma2(acc[10], w.x, hc.x); fma2(acc[10], w.y, hc.y);
            fma2(acc[11], w.x, hd.x); fma2(acc[11], w.y, hd.y);
            w = *(const ulonglong2*)(w3r + k);
            fma2(acc[12], w.x, ha.x); fma2(acc[12], w.y, ha.y);
            fma2(acc[13], w.x, hbv.x);fma2(acc[13], w.y, hbv.y);
            fma2(acc[14], w.x, hc.x); fma2(acc[14], w.y, hc.y);
            fma2(acc[15], w.x, hd.x); fma2(acc[15], w.y, hd.y);
        }

        // store partials (idx = g*4+j)
        float* rp = sR + (ks * 64 + slot) * RSTR;
        *(float4*)(rp + 0)  = make_float4(psum(acc[0]),  psum(acc[1]),  psum(acc[2]),  psum(acc[3]));
        *(float4*)(rp + 4)  = make_float4(psum(acc[4]),  psum(acc[5]),  psum(acc[6]),  psum(acc[7]));
        *(float4*)(rp + 8)  = make_float4(psum(acc[8]),  psum(acc[9]),  psum(acc[10]), psum(acc[11]));
        *(float4*)(rp + 12) = make_float4(psum(acc[12]), psum(acc[13]), psum(acc[14]), psum(acc[15]));
        __syncthreads();

        if (owner) {
            float tot[16];
#pragma unroll
            for (int i = 0; i < 16; i += 4) {
                float4 s0 = *(const float4*)(sR + (0 * 64 + slot) * RSTR + i);
                float4 s1 = *(const float4*)(sR + (1 * 64 + slot) * RSTR + i);
                float4 s2 = *(const float4*)(sR + (2 * 64 + slot) * RSTR + i);
                float4 s3 = *(const float4*)(sR + (3 * 64 + slot) * RSTR + i);
                tot[i + 0] = (s0.x + s1.x) + (s2.x + s3.x);
                tot[i + 1] = (s0.y + s1.y) + (s2.y + s3.y);
                tot[i + 2] = (s0.z + s1.z) + (s2.z + s3.z);
                tot[i + 3] = (s0.w + s1.w) + (s2.w + s3.w);
            }
            float* hw = g_h[(t + 1) & 1];
#pragma unroll
            for (int j = 0; j < 4; j++) {
                const float gi = prg[0 * 4 + j] + tot[0 * 4 + j];
                const float gf = prg[1 * 4 + j] + tot[1 * 4 + j];
                const float gc = prg[2 * 4 + j] + tot[2 * 4 + j];
                const float go = prg[3 * 4 + j] + tot[3 * 4 + j];
                const float si = __fdividef(1.f, 1.f + __expf(-gi));
                const float sf = __fdividef(1.f, 1.f + __expf(-gf));
                const float so = __fdividef(1.f, 1.f + __expf(-go));
                const float tg = 2.f * __fdividef(1.f, 1.f + __expf(-2.f * gc)) - 1.f;
                c[j] = sf * c[j] + si * tg;
                const float tc = 2.f * __fdividef(1.f, 1.f + __expf(-2.f * c[j])) - 1.f;
                const float hn = so * tc;
                xout[((size_t)(bbase + j) * Tn + t) * HIDn + u] = hn;
                hw[(bbase + j) * HIDn + u] = hn;
            }
        }
        group_sync(bb);
    }

    if (owner) {
        const float* hf = g_h[Tn & 1];
#pragma unroll
        for (int j = 0; j < 4; j++) {
            hout[(bbase + j) * HIDn + u] = hf[(bbase + j) * HIDn + u];
            cout[(bbase + j) * HIDn + u] = c[j];
        }
    }
}

// =============================================================================
extern "C" void kernel_launch(void* const* d_in, const int* in_sizes, int n_in,
                              void* d_out, int out_size)
{
    const float* x      = (const float*)d_in[0];
    const float* states = (const float*)d_in[1];
    const float* W_enc  = (const float*)d_in[2];
    const float* ln_g   = (const float*)d_in[3];
    const float* ln_b   = (const float*)d_in[4];
    const float* Wih1   = (const float*)d_in[5];
    const float* Whh1   = (const float*)d_in[6];
    const float* bih1   = (const float*)d_in[7];
    const float* bhh1   = (const float*)d_in[8];
    const float* Wih2   = (const float*)d_in[9];
    const float* Whh2   = (const float*)d_in[10];
    const float* bih2   = (const float*)d_in[11];
    const float* bhh2   = (const float*)d_in[12];
    const float* Wlin   = (const float*)d_in[13];
    const float* blin   = (const float*)d_in[14];
    const float* W_dec  = (const float*)d_in[15];

    float* out     = (float*)d_out;
    float* dstates = out + (size_t)Bn * FRAMEn * Tn;   // [4,B,HID]

    float *encoded, *buf, *pre, *x1;
    cudaGetSymbolAddress((void**)&encoded, g_encoded);
    cudaGetSymbolAddress((void**)&buf,     g_buf);
    cudaGetSymbolAddress((void**)&pre,     g_pre);
    cudaGetSymbolAddress((void**)&x1,      g_x1);

    static int smem_set = 0;
    const int LSTM_SMEM = (80 * WROW + 4 * 64 * RSTR) * 4;   // 185,600 B
    if (!smem_set) {
        cudaFuncSetAttribute(lstm_kernel,
                             cudaFuncAttributeMaxDynamicSharedMemorySize, LSTM_SMEM);
        smem_set = 1;
    }

    const int BH = Bn * HIDn;   // 32768

    // 1) encoder: encoded[b,t,o] = sum_c x[b,c,t] * W_enc[o,c]
    gemm_k<1, 0><<<dim3(ENCn / 128, Tn / 128, Bn), 256>>>(
        x, W_enc, encoded, 0, 0, 0,
        Tn, ENCn, FRAMEn, (size_t)FRAMEn * Tn, 0, (size_t)Tn * ENCn);

    // 2) layernorm -> enc_norm in g_buf
    ln_kernel<<<(Bn * Tn) / 8, 256>>>(encoded, buf, ln_g, ln_b);

    // 3) pre1 = enc_norm @ Wih1^T + bih1 + bhh1
    gemm_k<0, 1><<<dim3(G4n / 128, (Bn * Tn) / 128, 1), 256>>>(
        buf, Wih1, pre, 0, bih1, bhh1,
        Bn * Tn, G4n, ENCn, 0, 0, 0);

    // 4) LSTM layer 1
    lstm_kernel<<<NBLK, 256, LSTM_SMEM>>>(
        pre, Whh1, states + 0 * BH, states + 1 * BH,
        x1, dstates + 0 * BH, dstates + 1 * BH);

    // 5) pre2 = x1 @ Wih2^T + bih2 + bhh2
    gemm_k<0, 1><<<dim3(G4n / 128, (Bn * Tn) / 128, 1), 256>>>(
        x1, Wih2, pre, 0, bih2, bhh2,
        Bn * Tn, G4n, HIDn, 0, 0, 0);

    // 6) LSTM layer 2 (x2 reuses g_x1)
    lstm_kernel<<<NBLK, 256, LSTM_SMEM>>>(
        pre, Whh2, states + 2 * BH, states + 3 * BH,
        x1, dstates + 2 * BH, dstates + 3 * BH);

    // 7) est = sigmoid(x2 @ Wlin^T + blin) * encoded -> g_buf
    gemm_k<0, 2><<<dim3(ENCn / 128, (Bn * Tn) / 128, 1), 256>>>(
        x1, Wlin, buf, encoded, blin, 0,
        Bn * Tn, ENCn, HIDn, 0, 0, 0);

    // 8) decoder: decoded[b,f,t] = sum_o W_dec[f,o] * est[b,t,o]
    gemm_k<0, 0><<<dim3(Tn / 128, FRAMEn / 128, Bn), 256>>>(
        W_dec, buf, out, 0, 0, 0,
        FRAMEn, Tn, ENCn, 0, (size_t)Tn * ENCn, (size_t)FRAMEn * Tn);
}

// round 6
// speedup vs baseline: 7.5741x; 1.0015x over previous
#include <cuda_runtime.h>
#include <math.h>

#define Bn     64
#define Tn     1024
#define FRAMEn 512
#define ENCn   256
#define HIDn   512
#define G4n    2048
#define NBLK   128      // persistent LSTM grid (1 CTA/SM, co-resident)
#define GSIZE  32       // CTAs per barrier group (one batch-block)
#define WROW   516      // padded SMEM row stride (floats)
#define RSTR   20       // reduction slot stride (floats)

// ---------------- static device scratch (no cudaMalloc allowed) --------------
__device__ float g_encoded[(size_t)Bn * Tn * ENCn];
__device__ float g_buf[(size_t)Bn * Tn * ENCn];
__device__ float g_pre[(size_t)Bn * Tn * G4n];
__device__ float g_x1[(size_t)Bn * Tn * HIDn];
__device__ float g_h[2][Bn * HIDn];
__device__ unsigned g_cnt[4];
__device__ unsigned g_gen[4];

// ---------------- per-group software barrier (graph-replay safe) -------------
__device__ __forceinline__ void group_sync(int g) {
    __syncthreads();
    if (threadIdx.x == 0) {
        __threadfence();
        unsigned gen = ((volatile unsigned*)g_gen)[g];
        if (atomicAdd(&g_cnt[g], 1u) == GSIZE - 1) {
            g_cnt[g] = 0;
            __threadfence();
            atomicAdd(&g_gen[g], 1u);
        } else {
            while (((volatile unsigned*)g_gen)[g] == gen) { }
        }
        __threadfence();
    }
    __syncthreads();
}

// packed f32x2 helpers
__device__ __forceinline__ void fma2(unsigned long long& d,
                                     unsigned long long a, unsigned long long b) {
    asm("fma.rn.f32x2 %0, %1, %2, %0;" : "+l"(d) : "l"(a), "l"(b));
}
__device__ __forceinline__ unsigned long long bcast2(float v) {
    unsigned long long d;
    asm("mov.b64 %0, {%1, %1};" : "=l"(d) : "r"(__float_as_uint(v)));
    return d;
}
__device__ __forceinline__ float lo2(unsigned long long v) {
    return __uint_as_float((unsigned)v);
}
__device__ __forceinline__ float hi2(unsigned long long v) {
    return __uint_as_float((unsigned)(v >> 32));
}
__device__ __forceinline__ float psum(unsigned long long v) { return lo2(v) + hi2(v); }

// =============================================================================
// SIMT fp32 GEMM with f32x2-packed accumulators + SMEM double buffering.
//   C[M,N] = op(A) @ B^T    (B is [N,K] row-major)
//   TRANS_A==0: A is [M,K] row-major.   TRANS_A==1: A is [K,M] (lda = M).
//   EPI 0: C = acc   EPI 1: C = acc + bias1[n] + bias2[n]
//   EPI 2: C = sigmoid(acc + bias1[n]) * E[m,n]
// Tiles 128x128, BK=8, 256 threads, 8x8/thread.
// =============================================================================
template <int TRANS_A, int EPI>
__global__ void __launch_bounds__(256, 2) gemm_k(
    const float* __restrict__ A, const float* __restrict__ Bm,
    float* __restrict__ C, const float* __restrict__ E,
    const float* __restrict__ bias1, const float* __restrict__ bias2,
    int M, int N, int K, size_t sA, size_t sB, size_t sC)
{
    __shared__ float As[2][8 * 128];
    __shared__ float Bs[2][8 * 128];

    const int tid = threadIdx.x;
    const size_t z = blockIdx.z;
    const float* Ab = A + z * sA;
    const float* Bb = Bm + z * sB;
    float*       Cb = C + z * sC;
    const float* Eb = (EPI == 2) ? (E + z * sC) : (const float*)0;

    const int n0 = blockIdx.x * 128;
    const int m0 = blockIdx.y * 128;
    const int tx = tid & 15;
    const int ty = tid >> 4;

    const int row  = tid >> 1;
    const int half = tid & 1;
    const int kr   = tid >> 5;
    const int mc   = tid & 31;

    unsigned long long acc2[4][8];   // i-pairs x j
#pragma unroll
    for (int ip = 0; ip < 4; ip++)
#pragma unroll
        for (int j = 0; j < 8; j++) acc2[ip][j] = 0ull;

    // prefetch slab 0
    float4 pa, pb;
    if (TRANS_A) pa = *(const float4*)(Ab + (size_t)kr * M + m0 + mc * 4);
    else         pa = *(const float4*)(Ab + (size_t)(m0 + row) * K + half * 4);
    pb = *(const float4*)(Bb + (size_t)(n0 + row) * K + half * 4);

    // store slab 0 into buffer 0
    if (TRANS_A) {
        *(float4*)&As[0][kr * 128 + mc * 4] = pa;
    } else {
        As[0][(half * 4 + 0) * 128 + row] = pa.x;
        As[0][(half * 4 + 1) * 128 + row] = pa.y;
        As[0][(half * 4 + 2) * 128 + row] = pa.z;
        As[0][(half * 4 + 3) * 128 + row] = pa.w;
    }
    Bs[0][(half * 4 + 0) * 128 + row] = pb.x;
    Bs[0][(half * 4 + 1) * 128 + row] = pb.y;
    Bs[0][(half * 4 + 2) * 128 + row] = pb.z;
    Bs[0][(half * 4 + 3) * 128 + row] = pb.w;
    __syncthreads();

    int buf = 0;
    for (int k0 = 0; k0 < K; k0 += 8) {
        const bool more = (k0 + 8 < K);
        if (more) {   // prefetch next slab into registers
            if (TRANS_A) pa = *(const float4*)(Ab + (size_t)(k0 + 8 + kr) * M + m0 + mc * 4);
            else         pa = *(const float4*)(Ab + (size_t)(m0 + row) * K + k0 + 8 + half * 4);
            pb = *(const float4*)(Bb + (size_t)(n0 + row) * K + k0 + 8 + half * 4);
        }

#pragma unroll
        for (int kk = 0; kk < 8; kk++) {
            // a-pairs come naturally from float4 loads
            ulonglong2 aA = *(const ulonglong2*)&As[buf][kk * 128 + ty * 8];
            ulonglong2 aB = *(const ulonglong2*)&As[buf][kk * 128 + ty * 8 + 4];
            float bv[8];
            *(float4*)(bv)     = *(const float4*)&Bs[buf][kk * 128 + tx * 8];
            *(float4*)(bv + 4) = *(const float4*)&Bs[buf][kk * 128 + tx * 8 + 4];
#pragma unroll
            for (int j = 0; j < 8; j++) {
                const unsigned long long bj = bcast2(bv[j]);
                fma2(acc2[0][j], aA.x, bj);
                fma2(acc2[1][j], aA.y, bj);
                fma2(acc2[2][j], aB.x, bj);
                fma2(acc2[3][j], aB.y, bj);
            }
        }

        if (more) {   // write next slab into the other buffer, single sync
            const int nb = buf ^ 1;
            if (TRANS_A) {
                *(float4*)&As[nb][kr * 128 + mc * 4] = pa;
            } else {
                As[nb][(half * 4 + 0) * 128 + row] = pa.x;
                As[nb][(half * 4 + 1) * 128 + row] = pa.y;
                As[nb][(half * 4 + 2) * 128 + row] = pa.z;
                As[nb][(half * 4 + 3) * 128 + row] = pa.w;
            }
            Bs[nb][(half * 4 + 0) * 128 + row] = pb.x;
            Bs[nb][(half * 4 + 1) * 128 + row] = pb.y;
            Bs[nb][(half * 4 + 2) * 128 + row] = pb.z;
            Bs[nb][(half * 4 + 3) * 128 + row] = pb.w;
            __syncthreads();
            buf = nb;
        }
    }

    // unpack and run epilogue
#pragma unroll
    for (int ip = 0; ip < 4; ip++) {
#pragma unroll
        for (int hf = 0; hf < 2; hf++) {
            const int i = ip * 2 + hf;
            const int m = m0 + ty * 8 + i;
            float* crow = Cb + (size_t)m * N;
#pragma unroll
            for (int j = 0; j < 8; j += 4) {
                const int n = n0 + tx * 8 + j;
                float4 v;
                v.x = hf ? hi2(acc2[ip][j])     : lo2(acc2[ip][j]);
                v.y = hf ? hi2(acc2[ip][j + 1]) : lo2(acc2[ip][j + 1]);
                v.z = hf ? hi2(acc2[ip][j + 2]) : lo2(acc2[ip][j + 2]);
                v.w = hf ? hi2(acc2[ip][j + 3]) : lo2(acc2[ip][j + 3]);
                if (EPI == 1) {
                    v.x += bias1[n]     + bias2[n];
                    v.y += bias1[n + 1] + bias2[n + 1];
                    v.z += bias1[n + 2] + bias2[n + 2];
                    v.w += bias1[n + 3] + bias2[n + 3];
                } else if (EPI == 2) {
                    float4 e = *(const float4*)(Eb + (size_t)m * N + n);
                    v.x = e.x / (1.f + expf(-(v.x + bias1[n])));
                    v.y = e.y / (1.f + expf(-(v.y + bias1[n + 1])));
                    v.z = e.z / (1.f + expf(-(v.z + bias1[n + 2])));
                    v.w = e.w / (1.f + expf(-(v.w + bias1[n + 3])));
                }
                *(float4*)(crow + n) = v;
            }
        }
    }
}

// ---------------- layernorm over last dim (256), one warp per row ------------
__global__ void __launch_bounds__(256) ln_kernel(
    const float* __restrict__ in, float* __restrict__ out,
    const float* __restrict__ gam, const float* __restrict__ bet)
{
    const int row  = blockIdx.x * 8 + (threadIdx.x >> 5);
    const int lane = threadIdx.x & 31;
    const float* r = in + (size_t)row * ENCn + lane * 8;
    float4 a  = *(const float4*)r;
    float4 b4 = *(const float4*)(r + 4);
    float s  = a.x + a.y + a.z + a.w + b4.x + b4.y + b4.z + b4.w;
    float sq = a.x*a.x + a.y*a.y + a.z*a.z + a.w*a.w
             + b4.x*b4.x + b4.y*b4.y + b4.z*b4.z + b4.w*b4.w;
#pragma unroll
    for (int o = 16; o; o >>= 1) {
        s  += __shfl_xor_sync(0xFFFFFFFFu, s,  o);
        sq += __shfl_xor_sync(0xFFFFFFFFu, sq, o);
    }
    const float mu   = s * (1.f / 256.f);
    const float var  = sq * (1.f / 256.f) - mu * mu;
    const float rstd = rsqrtf(var + 1e-5f);

    float* o = out + (size_t)row * ENCn + lane * 8;
    const float* gg = gam + lane * 8;
    const float* bb = bet + lane * 8;
    float4 ga = *(const float4*)gg,  gb  = *(const float4*)(gg + 4);
    float4 ba = *(const float4*)bb,  bbv = *(const float4*)(bb + 4);
    float4 o1, o2;
    o1.x = (a.x  - mu) * rstd * ga.x + ba.x;
    o1.y = (a.y  - mu) * rstd * ga.y + ba.y;
    o1.z = (a.z  - mu) * rstd * ga.z + ba.z;
    o1.w = (a.w  - mu) * rstd * ga.w + ba.w;
    o2.x = (b4.x - mu) * rstd * gb.x + bbv.x;
    o2.y = (b4.y - mu) * rstd * gb.y + bbv.y;
    o2.z = (b4.z - mu) * rstd * gb.z + bbv.z;
    o2.w = (b4.w - mu) * rstd * gb.w + bbv.w;
    *(float4*)o       = o1;
    *(float4*)(o + 4) = o2;
}

// ---------------- persistent LSTM layer, v4 ----------------------------------
// Grid: 128 CTAs = 32 u-blocks (16 units) x 4 b-blocks (16 batches).
// Main loop: thread=(unit ul, k-quarter ks, 4 batches), partials to SMEM.
// Epilogue: all 256 threads, one (b,u) each; per-thread pre prefetch + c state.
__global__ void __launch_bounds__(256) lstm_kernel(
    const float* __restrict__ pre, const float* __restrict__ Whh,
    const float* __restrict__ h0,  const float* __restrict__ c0,
    float* __restrict__ xout, float* __restrict__ hout, float* __restrict__ cout)
{
    extern __shared__ float sm[];
    float* sW = sm;                    // 64 rows x WROW
    float* sH = sm + 64 * WROW;        // 16 rows x WROW
    float* sR = sm + 80 * WROW;        // 4*64 slots x RSTR

    const int tid  = threadIdx.x, cta = blockIdx.x;
    const int ub   = cta & 31, bb = cta >> 5;
    const int warp = tid >> 5, lane = tid & 31;
    // main-loop mapping
    const int ks    = warp & 3;
    const int bq_hi = warp >> 2;
    const int ul    = lane & 15;
    const int bq_lo = lane >> 4;
    const int bq    = bq_hi * 2 + bq_lo;
    const int slot  = bq * 16 + ul;
    // epilogue mapping: one (b,u) per thread
    const int e_u   = tid & 15;
    const int e_b   = tid >> 4;                    // 0..15
    const int eslot = (e_b >> 2) * 16 + e_u;
    const int ej    = e_b & 3;
    const int gb    = bb * 16 + e_b;               // global batch
    const int gu    = ub * 16 + e_u;               // global unit

    // load Whh slice
    for (int i = tid; i < 64 * 128; i += 256) {
        const int r  = i >> 7;
        const int k4 = i & 127;
        const int g  = r >> 4;
        const int uu = ub * 16 + (r & 15);
        *(float4*)(sW + r * WROW + k4 * 4) =
            *(const float4*)(Whh + ((size_t)(g * HIDn + uu)) * HIDn + k4 * 4);
    }
    g_h[0][cta * 256 + tid] = h0[cta * 256 + tid];
    float c = c0[gb * HIDn + gu];
    float hlast = 0.f;
    group_sync(bb);

    const float* w0r = sW + (0 * 16 + ul) * WROW + ks * 128;
    const float* w1r = sW + (1 * 16 + ul) * WROW + ks * 128;
    const float* w2r = sW + (2 * 16 + ul) * WROW + ks * 128;
    const float* w3r = sW + (3 * 16 + ul) * WROW + ks * 128;
    const float* hb0 = sH + (bq * 4 + 0) * WROW + ks * 128;
    const float* hb1 = sH + (bq * 4 + 1) * WROW + ks * 128;
    const float* hb2 = sH + (bq * 4 + 2) * WROW + ks * 128;
    const float* hb3 = sH + (bq * 4 + 3) * WROW + ks * 128;

    for (int t = 0; t < Tn; t++) {
        // cooperative h -> SMEM
        const float* hr = g_h[t & 1] + (size_t)bb * 16 * HIDn;
        for (int i = tid; i < 16 * 128; i += 256) {
            const int rr = i >> 7, k4 = i & 127;
            *(float4*)(sH + rr * WROW + k4 * 4) =
                *(const float4*)(hr + (size_t)rr * HIDn + k4 * 4);
        }
        // per-thread pre prefetch (consumed at epilogue -> latency hidden)
        const float* pb = pre + ((size_t)gb * Tn + t) * G4n + gu;
        const float p0 = pb[0], p1 = pb[512], p2 = pb[1024], p3 = pb[1536];
        __syncthreads();

        unsigned long long acc[16];
#pragma unroll
        for (int i = 0; i < 16; i++) acc[i] = 0ull;

#pragma unroll 4
        for (int q = 0; q < 32; q++) {
            const int k = q * 4;
            const ulonglong2 ha  = *(const ulonglong2*)(hb0 + k);
            const ulonglong2 hbv = *(const ulonglong2*)(hb1 + k);
            const ulonglong2 hc  = *(const ulonglong2*)(hb2 + k);
            const ulonglong2 hd  = *(const ulonglong2*)(hb3 + k);
            ulonglong2 w;
            w = *(const ulonglong2*)(w0r + k);
            fma2(acc[0], w.x, ha.x);  fma2(acc[0], w.y, ha.y);
            fma2(acc[1], w.x, hbv.x); fma2(acc[1], w.y, hbv.y);
            fma2(acc[2], w.x, hc.x);  fma2(acc[2], w.y, hc.y);
            fma2(acc[3], w.x, hd.x);  fma2(acc[3], w.y, hd.y);
            w = *(const ulonglong2*)(w1r + k);
            fma2(acc[4], w.x, ha.x);  fma2(acc[4], w.y, ha.y);
            fma2(acc[5], w.x, hbv.x); fma2(acc[5], w.y, hbv.y);
            fma2(acc[6], w.x, hc.x);  fma2(acc[6], w.y, hc.y);
            fma2(acc[7], w.x, hd.x);  fma2(acc[7], w.y, hd.y);
            w = *(const ulonglong2*)(w2r + k);
            fma2(acc[8], w.x, ha.x);  fma2(acc[8], w.y, ha.y);
            fma2(acc[9], w.x, hbv.x); fma2(acc[9], w.y, hbv.y);
            fma2(acc[10], w.x, hc.x); fma2(acc[10], w.y, hc.y);
            fma2(acc[11], w.x, hd.x); fma2(acc[11], w.y, hd.y);
            w = *(const ulonglong2*)(w3r + k);
            fma2(acc[12], w.x, ha.x); fma2(acc[12], w.y, ha.y);
            fma2(acc[13], w.x, hbv.x);fma2(acc[13], w.y, hbv.y);
            fma2(acc[14], w.x, hc.x); fma2(acc[14], w.y, hc.y);
            fma2(acc[15], w.x, hd.x); fma2(acc[15], w.y, hd.y);
        }

        // store partials transposed: for each j (batch), float4 of gates 0..3
        float* rp = sR + (ks * 64 + slot) * RSTR;
        *(float4*)(rp + 0)  = make_float4(psum(acc[0]), psum(acc[4]), psum(acc[8]),  psum(acc[12]));
        *(float4*)(rp + 4)  = make_float4(psum(acc[1]), psum(acc[5]), psum(acc[9]),  psum(acc[13]));
        *(float4*)(rp + 8)  = make_float4(psum(acc[2]), psum(acc[6]), psum(acc[10]), psum(acc[14]));
        *(float4*)(rp + 12) = make_float4(psum(acc[3]), psum(acc[7]), psum(acc[11]), psum(acc[15]));
        __syncthreads();

        // distributed epilogue: every thread finishes one (b,u)
        {
            const float4 s0 = *(const float4*)(sR + (0 * 64 + eslot) * RSTR + ej * 4);
            const float4 s1 = *(const float4*)(sR + (1 * 64 + eslot) * RSTR + ej * 4);
            const float4 s2 = *(const float4*)(sR + (2 * 64 + eslot) * RSTR + ej * 4);
            const float4 s3 = *(const float4*)(sR + (3 * 64 + eslot) * RSTR + ej * 4);
            const float gi = p0 + ((s0.x + s1.x) + (s2.x + s3.x));
            const float gf = p1 + ((s0.y + s1.y) + (s2.y + s3.y));
            const float gc = p2 + ((s0.z + s1.z) + (s2.z + s3.z));
            const float go = p3 + ((s0.w + s1.w) + (s2.w + s3.w));
            const float si = __fdividef(1.f, 1.f + __expf(-gi));
            const float sf = __fdividef(1.f, 1.f + __expf(-gf));
            const float so = __fdividef(1.f, 1.f + __expf(-go));
            const float tg = 2.f * __fdividef(1.f, 1.f + __expf(-2.f * gc)) - 1.f;
            c = sf * c + si * tg;
            const float tc = 2.f * __fdividef(1.f, 1.f + __expf(-2.f * c)) - 1.f;
            const float hn = so * tc;
            hlast = hn;
            xout[((size_t)gb * Tn + t) * HIDn + gu] = hn;
            g_h[(t + 1) & 1][gb * HIDn + gu] = hn;
        }
        group_sync(bb);
    }

    hout[gb * HIDn + gu] = hlast;
    cout[gb * HIDn + gu] = c;
}

// =============================================================================
extern "C" void kernel_launch(void* const* d_in, const int* in_sizes, int n_in,
                              void* d_out, int out_size)
{
    const float* x      = (const float*)d_in[0];
    const float* states = (const float*)d_in[1];
    const float* W_enc  = (const float*)d_in[2];
    const float* ln_g   = (const float*)d_in[3];
    const float* ln_b   = (const float*)d_in[4];
    const float* Wih1   = (const float*)d_in[5];
    const float* Whh1   = (const float*)d_in[6];
    const float* bih1   = (const float*)d_in[7];
    const float* bhh1   = (const float*)d_in[8];
    const float* Wih2   = (const float*)d_in[9];
    const float* Whh2   = (const float*)d_in[10];
    const float* bih2   = (const float*)d_in[11];
    const float* bhh2   = (const float*)d_in[12];
    const float* Wlin   = (const float*)d_in[13];
    const float* blin   = (const float*)d_in[14];
    const float* W_dec  = (const float*)d_in[15];

    float* out     = (float*)d_out;
    float* dstates = out + (size_t)Bn * FRAMEn * Tn;   // [4,B,HID]

    float *encoded, *buf, *pre, *x1;
    cudaGetSymbolAddress((void**)&encoded, g_encoded);
    cudaGetSymbolAddress((void**)&buf,     g_buf);
    cudaGetSymbolAddress((void**)&pre,     g_pre);
    cudaGetSymbolAddress((void**)&x1,      g_x1);

    static int smem_set = 0;
    const int LSTM_SMEM = (80 * WROW + 4 * 64 * RSTR) * 4;   // 185,600 B
    if (!smem_set) {
        cudaFuncSetAttribute(lstm_kernel,
                             cudaFuncAttributeMaxDynamicSharedMemorySize, LSTM_SMEM);
        smem_set = 1;
    }

    const int BH = Bn * HIDn;   // 32768

    // 1) encoder: encoded[b,t,o] = sum_c x[b,c,t] * W_enc[o,c]
    gemm_k<1, 0><<<dim3(ENCn / 128, Tn / 128, Bn), 256>>>(
        x, W_enc, encoded, 0, 0, 0,
        Tn, ENCn, FRAMEn, (size_t)FRAMEn * Tn, 0, (size_t)Tn * ENCn);

    // 2) layernorm -> enc_norm in g_buf
    ln_kernel<<<(Bn * Tn) / 8, 256>>>(encoded, buf, ln_g, ln_b);

    // 3) pre1 = enc_norm @ Wih1^T + bih1 + bhh1
    gemm_k<0, 1><<<dim3(G4n / 128, (Bn * Tn) / 128, 1), 256>>>(
        buf, Wih1, pre, 0, bih1, bhh1,
        Bn * Tn, G4n, ENCn, 0, 0, 0);

    // 4) LSTM layer 1
    lstm_kernel<<<NBLK, 256, LSTM_SMEM>>>(
        pre, Whh1, states + 0 * BH, states + 1 * BH,
        x1, dstates + 0 * BH, dstates + 1 * BH);

    // 5) pre2 = x1 @ Wih2^T + bih2 + bhh2
    gemm_k<0, 1><<<dim3(G4n / 128, (Bn * Tn) / 128, 1), 256>>>(
        x1, Wih2, pre, 0, bih2, bhh2,
        Bn * Tn, G4n, HIDn, 0, 0, 0);

    // 6) LSTM layer 2 (x2 reuses g_x1)
    lstm_kernel<<<NBLK, 256, LSTM_SMEM>>>(
        pre, Whh2, states + 2 * BH, states + 3 * BH,
        x1, dstates + 2 * BH, dstates + 3 * BH);

    // 7) est = sigmoid(x2 @ Wlin^T + blin) * encoded -> g_buf
    gemm_k<0, 2><<<dim3(ENCn / 128, (Bn * Tn) / 128, 1), 256>>>(
        x1, Wlin, buf, encoded, blin, 0,
        Bn * Tn, ENCn, HIDn, 0, 0, 0);

    // 8) decoder: decoded[b,f,t] = sum_o W_dec[f,o] * est[b,t,o]
    gemm_k<0, 0><<<dim3(Tn / 128, FRAMEn / 128, Bn), 256>>>(
        W_dec, buf, out, 0, 0, 0,
        FRAMEn, Tn, ENCn, 0, (size_t)Tn * ENCn, (size_t)FRAMEn * Tn);
}

// round 7
// speedup vs baseline: 7.6522x; 1.0103x over previous
#include <cuda_runtime.h>
#include <math.h>

#define Bn     64
#define Tn     1024
#define FRAMEn 512
#define ENCn   256
#define HIDn   512
#define G4n    2048
#define NBLK   128      // persistent LSTM grid (1 CTA/SM, co-resident)
#define GSIZE  32       // CTAs per barrier group (one batch-block)
#define WROW   516      // padded SMEM row stride (floats)
#define RSTR   20       // reduction slot stride (floats)

// ---------------- static device scratch (no cudaMalloc allowed) --------------
__device__ float g_encoded[(size_t)Bn * Tn * ENCn];
__device__ float g_buf[(size_t)Bn * Tn * ENCn];
__device__ float g_pre[(size_t)Bn * Tn * G4n];
__device__ float g_x1[(size_t)Bn * Tn * HIDn];
__device__ float g_h[2][Bn * HIDn];
__device__ unsigned g_cnt[4];
__device__ unsigned g_gen[4];

// ---------------- acquire/release primitives (no MEMBAR drains) --------------
__device__ __forceinline__ unsigned atom_add_release(unsigned* p, unsigned v) {
    unsigned old;
    asm volatile("atom.add.release.gpu.global.u32 %0, [%1], %2;"
                 : "=r"(old) : "l"(p), "r"(v) : "memory");
    return old;
}
__device__ __forceinline__ unsigned ld_acquire(const unsigned* p) {
    unsigned v;
    asm volatile("ld.acquire.gpu.global.u32 %0, [%1];" : "=r"(v) : "l"(p) : "memory");
    return v;
}
__device__ __forceinline__ void st_relaxed(unsigned* p, unsigned v) {
    asm volatile("st.relaxed.gpu.global.u32 [%0], %1;" :: "l"(p), "r"(v) : "memory");
}
__device__ __forceinline__ void red_add_release(unsigned* p, unsigned v) {
    asm volatile("red.add.release.gpu.global.u32 [%0], %1;" :: "l"(p), "r"(v) : "memory");
}

// per-group barrier: bar.sync + release-arrive + acquire-poll (CG grid.sync pattern)
__device__ __forceinline__ void group_sync(int g) {
    __syncthreads();
    if (threadIdx.x == 0) {
        const unsigned gen = ld_acquire(&g_gen[g]);
        if (atom_add_release(&g_cnt[g], 1u) == GSIZE - 1) {
            st_relaxed(&g_cnt[g], 0u);          // ordered before gen bump by release below
            red_add_release(&g_gen[g], 1u);
        } else {
            while (ld_acquire(&g_gen[g]) == gen) { }
        }
    }
    __syncthreads();
}

// packed f32x2 helpers
__device__ __forceinline__ void fma2(unsigned long long& d,
                                     unsigned long long a, unsigned long long b) {
    asm("fma.rn.f32x2 %0, %1, %2, %0;" : "+l"(d) : "l"(a), "l"(b));
}
__device__ __forceinline__ unsigned long long bcast2(float v) {
    unsigned long long d;
    asm("mov.b64 %0, {%1, %1};" : "=l"(d) : "r"(__float_as_uint(v)));
    return d;
}
__device__ __forceinline__ float lo2(unsigned long long v) {
    return __uint_as_float((unsigned)v);
}
__device__ __forceinline__ float hi2(unsigned long long v) {
    return __uint_as_float((unsigned)(v >> 32));
}
__device__ __forceinline__ float psum(unsigned long long v) { return lo2(v) + hi2(v); }

// =============================================================================
// SIMT fp32 GEMM with f32x2-packed accumulators + SMEM double buffering.
//   C[M,N] = op(A) @ B^T    (B is [N,K] row-major)
// =============================================================================
template <int TRANS_A, int EPI>
__global__ void __launch_bounds__(256, 2) gemm_k(
    const float* __restrict__ A, const float* __restrict__ Bm,
    float* __restrict__ C, const float* __restrict__ E,
    const float* __restrict__ bias1, const float* __restrict__ bias2,
    int M, int N, int K, size_t sA, size_t sB, size_t sC)
{
    __shared__ float As[2][8 * 128];
    __shared__ float Bs[2][8 * 128];

    const int tid = threadIdx.x;
    const size_t z = blockIdx.z;
    const float* Ab = A + z * sA;
    const float* Bb = Bm + z * sB;
    float*       Cb = C + z * sC;
    const float* Eb = (EPI == 2) ? (E + z * sC) : (const float*)0;

    const int n0 = blockIdx.x * 128;
    const int m0 = blockIdx.y * 128;
    const int tx = tid & 15;
    const int ty = tid >> 4;

    const int row  = tid >> 1;
    const int half = tid & 1;
    const int kr   = tid >> 5;
    const int mc   = tid & 31;

    unsigned long long acc2[4][8];
#pragma unroll
    for (int ip = 0; ip < 4; ip++)
#pragma unroll
        for (int j = 0; j < 8; j++) acc2[ip][j] = 0ull;

    float4 pa, pb;
    if (TRANS_A) pa = *(const float4*)(Ab + (size_t)kr * M + m0 + mc * 4);
    else         pa = *(const float4*)(Ab + (size_t)(m0 + row) * K + half * 4);
    pb = *(const float4*)(Bb + (size_t)(n0 + row) * K + half * 4);

    if (TRANS_A) {
        *(float4*)&As[0][kr * 128 + mc * 4] = pa;
    } else {
        As[0][(half * 4 + 0) * 128 + row] = pa.x;
        As[0][(half * 4 + 1) * 128 + row] = pa.y;
        As[0][(half * 4 + 2) * 128 + row] = pa.z;
        As[0][(half * 4 + 3) * 128 + row] = pa.w;
    }
    Bs[0][(half * 4 + 0) * 128 + row] = pb.x;
    Bs[0][(half * 4 + 1) * 128 + row] = pb.y;
    Bs[0][(half * 4 + 2) * 128 + row] = pb.z;
    Bs[0][(half * 4 + 3) * 128 + row] = pb.w;
    __syncthreads();

    int buf = 0;
    for (int k0 = 0; k0 < K; k0 += 8) {
        const bool more = (k0 + 8 < K);
        if (more) {
            if (TRANS_A) pa = *(const float4*)(Ab + (size_t)(k0 + 8 + kr) * M + m0 + mc * 4);
            else         pa = *(const float4*)(Ab + (size_t)(m0 + row) * K + k0 + 8 + half * 4);
            pb = *(const float4*)(Bb + (size_t)(n0 + row) * K + k0 + 8 + half * 4);
        }

#pragma unroll
        for (int kk = 0; kk < 8; kk++) {
            ulonglong2 aA = *(const ulonglong2*)&As[buf][kk * 128 + ty * 8];
            ulonglong2 aB = *(const ulonglong2*)&As[buf][kk * 128 + ty * 8 + 4];
            float bv[8];
            *(float4*)(bv)     = *(const float4*)&Bs[buf][kk * 128 + tx * 8];
            *(float4*)(bv + 4) = *(const float4*)&Bs[buf][kk * 128 + tx * 8 + 4];
#pragma unroll
            for (int j = 0; j < 8; j++) {
                const unsigned long long bj = bcast2(bv[j]);
                fma2(acc2[0][j], aA.x, bj);
                fma2(acc2[1][j], aA.y, bj);
                fma2(acc2[2][j], aB.x, bj);
                fma2(acc2[3][j], aB.y, bj);
            }
        }

        if (more) {
            const int nb = buf ^ 1;
            if (TRANS_A) {
                *(float4*)&As[nb][kr * 128 + mc * 4] = pa;
            } else {
                As[nb][(half * 4 + 0) * 128 + row] = pa.x;
                As[nb][(half * 4 + 1) * 128 + row] = pa.y;
                As[nb][(half * 4 + 2) * 128 + row] = pa.z;
                As[nb][(half * 4 + 3) * 128 + row] = pa.w;
            }
            Bs[nb][(half * 4 + 0) * 128 + row] = pb.x;
            Bs[nb][(half * 4 + 1) * 128 + row] = pb.y;
            Bs[nb][(half * 4 + 2) * 128 + row] = pb.z;
            Bs[nb][(half * 4 + 3) * 128 + row] = pb.w;
            __syncthreads();
            buf = nb;
        }
    }

#pragma unroll
    for (int ip = 0; ip < 4; ip++) {
#pragma unroll
        for (int hf = 0; hf < 2; hf++) {
            const int i = ip * 2 + hf;
            const int m = m0 + ty * 8 + i;
            float* crow = Cb + (size_t)m * N;
#pragma unroll
            for (int j = 0; j < 8; j += 4) {
                const int n = n0 + tx * 8 + j;
                float4 v;
                v.x = hf ? hi2(acc2[ip][j])     : lo2(acc2[ip][j]);
                v.y = hf ? hi2(acc2[ip][j + 1]) : lo2(acc2[ip][j + 1]);
                v.z = hf ? hi2(acc2[ip][j + 2]) : lo2(acc2[ip][j + 2]);
                v.w = hf ? hi2(acc2[ip][j + 3]) : lo2(acc2[ip][j + 3]);
                if (EPI == 1) {
                    v.x += bias1[n]     + bias2[n];
                    v.y += bias1[n + 1] + bias2[n + 1];
                    v.z += bias1[n + 2] + bias2[n + 2];
                    v.w += bias1[n + 3] + bias2[n + 3];
                } else if (EPI == 2) {
                    float4 e = *(const float4*)(Eb + (size_t)m * N + n);
                    v.x = e.x / (1.f + expf(-(v.x + bias1[n])));
                    v.y = e.y / (1.f + expf(-(v.y + bias1[n + 1])));
                    v.z = e.z / (1.f + expf(-(v.z + bias1[n + 2])));
                    v.w = e.w / (1.f + expf(-(v.w + bias1[n + 3])));
                }
                *(float4*)(crow + n) = v;
            }
        }
    }
}

// ---------------- layernorm over last dim (256), one warp per row ------------
__global__ void __launch_bounds__(256) ln_kernel(
    const float* __restrict__ in, float* __restrict__ out,
    const float* __restrict__ gam, const float* __restrict__ bet)
{
    const int row  = blockIdx.x * 8 + (threadIdx.x >> 5);
    const int lane = threadIdx.x & 31;
    const float* r = in + (size_t)row * ENCn + lane * 8;
    float4 a  = *(const float4*)r;
    float4 b4 = *(const float4*)(r + 4);
    float s  = a.x + a.y + a.z + a.w + b4.x + b4.y + b4.z + b4.w;
    float sq = a.x*a.x + a.y*a.y + a.z*a.z + a.w*a.w
             + b4.x*b4.x + b4.y*b4.y + b4.z*b4.z + b4.w*b4.w;
#pragma unroll
    for (int o = 16; o; o >>= 1) {
        s  += __shfl_xor_sync(0xFFFFFFFFu, s,  o);
        sq += __shfl_xor_sync(0xFFFFFFFFu, sq, o);
    }
    const float mu   = s * (1.f / 256.f);
    const float var  = sq * (1.f / 256.f) - mu * mu;
    const float rstd = rsqrtf(var + 1e-5f);

    float* o = out + (size_t)row * ENCn + lane * 8;
    const float* gg = gam + lane * 8;
    const float* bb = bet + lane * 8;
    float4 ga = *(const float4*)gg,  gb  = *(const float4*)(gg + 4);
    float4 ba = *(const float4*)bb,  bbv = *(const float4*)(bb + 4);
    float4 o1, o2;
    o1.x = (a.x  - mu) * rstd * ga.x + ba.x;
    o1.y = (a.y  - mu) * rstd * ga.y + ba.y;
    o1.z = (a.z  - mu) * rstd * ga.z + ba.z;
    o1.w = (a.w  - mu) * rstd * ga.w + ba.w;
    o2.x = (b4.x - mu) * rstd * gb.x + bbv.x;
    o2.y = (b4.y - mu) * rstd * gb.y + bbv.y;
    o2.z = (b4.z - mu) * rstd * gb.z + bbv.z;
    o2.w = (b4.w - mu) * rstd * gb.w + bbv.w;
    *(float4*)o       = o1;
    *(float4*)(o + 4) = o2;
}

// ---------------- persistent LSTM layer, v5 (512 threads, 8-way k) -----------
// Grid: 128 CTAs = 32 u-blocks (16 units) x 4 b-blocks (16 batches).
// 16 warps: warp = bq_hi*8 + ks; lane: ul(16) x bq_lo(2). Thread = (unit, 4
// batches, k-eighth). Epilogue: tid<256, one (b,u) each, 8-way partial sum.
__global__ void __launch_bounds__(512) lstm_kernel(
    const float* __restrict__ pre, const float* __restrict__ Whh,
    const float* __restrict__ h0,  const float* __restrict__ c0,
    float* __restrict__ xout, float* __restrict__ hout, float* __restrict__ cout)
{
    extern __shared__ float sm[];
    float* sW = sm;                    // 64 rows x WROW
    float* sH = sm + 64 * WROW;        // 16 rows x WROW
    float* sR = sm + 80 * WROW;        // 8*64 slots x RSTR

    const int tid  = threadIdx.x, cta = blockIdx.x;
    const int ub   = cta & 31, bb = cta >> 5;
    const int warp = tid >> 5, lane = tid & 31;
    // main-loop mapping
    const int ks    = warp & 7;                    // k-eighth
    const int bq_hi = warp >> 3;                   // 0..1
    const int ul    = lane & 15;
    const int bq_lo = lane >> 4;
    const int bq    = bq_hi * 2 + bq_lo;           // 0..3
    const int slot  = bq * 16 + ul;                // 0..63
    // epilogue mapping (tid < 256): one (b,u) per thread
    const int e_u   = tid & 15;
    const int e_b   = (tid >> 4) & 15;
    const int eslot = (e_b >> 2) * 16 + e_u;
    const int ej    = e_b & 3;
    const int gb    = bb * 16 + e_b;
    const int gu    = ub * 16 + e_u;
    const bool epi  = (tid < 256);

    // load Whh slice: rows {g*512 + (ub*16+r)}
    for (int i = tid; i < 64 * 128; i += 512) {
        const int r  = i >> 7;
        const int k4 = i & 127;
        const int g  = r >> 4;
        const int uu = ub * 16 + (r & 15);
        *(float4*)(sW + r * WROW + k4 * 4) =
            *(const float4*)(Whh + ((size_t)(g * HIDn + uu)) * HIDn + k4 * 4);
    }
    if (epi) g_h[0][cta * 256 + tid] = h0[cta * 256 + tid];
    float c = 0.f, hlast = 0.f;
    if (epi) c = c0[gb * HIDn + gu];
    group_sync(bb);

    const float* w0r = sW + (0 * 16 + ul) * WROW + ks * 64;
    const float* w1r = sW + (1 * 16 + ul) * WROW + ks * 64;
    const float* w2r = sW + (2 * 16 + ul) * WROW + ks * 64;
    const float* w3r = sW + (3 * 16 + ul) * WROW + ks * 64;
    const float* hb0 = sH + (bq * 4 + 0) * WROW + ks * 64;
    const float* hb1 = sH + (bq * 4 + 1) * WROW + ks * 64;
    const float* hb2 = sH + (bq * 4 + 2) * WROW + ks * 64;
    const float* hb3 = sH + (bq * 4 + 3) * WROW + ks * 64;

    for (int t = 0; t < Tn; t++) {
        // cooperative h -> SMEM (2048 float4s, 512 threads, 4 iters)
        const float* hr = g_h[t & 1] + (size_t)bb * 16 * HIDn;
        for (int i = tid; i < 16 * 128; i += 512) {
            const int rr = i >> 7, k4 = i & 127;
            *(float4*)(sH + rr * WROW + k4 * 4) =
                *(const float4*)(hr + (size_t)rr * HIDn + k4 * 4);
        }
        // per-thread pre prefetch (epilogue threads only; consumed post-compute)
        float p0 = 0.f, p1 = 0.f, p2 = 0.f, p3 = 0.f;
        if (epi) {
            const float* pb = pre + ((size_t)gb * Tn + t) * G4n + gu;
            p0 = pb[0]; p1 = pb[512]; p2 = pb[1024]; p3 = pb[1536];
        }
        __syncthreads();

        unsigned long long acc[16];
#pragma unroll
        for (int i = 0; i < 16; i++) acc[i] = 0ull;

#pragma unroll 8
        for (int q = 0; q < 16; q++) {
            const int k = q * 4;
            const ulonglong2 ha  = *(const ulonglong2*)(hb0 + k);
            const ulonglong2 hbv = *(const ulonglong2*)(hb1 + k);
            const ulonglong2 hc  = *(const ulonglong2*)(hb2 + k);
            const ulonglong2 hd  = *(const ulonglong2*)(hb3 + k);
            ulonglong2 w;
            w = *(const ulonglong2*)(w0r + k);
            fma2(acc[0], w.x, ha.x);  fma2(acc[0], w.y, ha.y);
            fma2(acc[1], w.x, hbv.x); fma2(acc[1], w.y, hbv.y);
            fma2(acc[2], w.x, hc.x);  fma2(acc[2], w.y, hc.y);
            fma2(acc[3], w.x, hd.x);  fma2(acc[3], w.y, hd.y);
            w = *(const ulonglong2*)(w1r + k);
            fma2(acc[4], w.x, ha.x);  fma2(acc[4], w.y, ha.y);
            fma2(acc[5], w.x, hbv.x); fma2(acc[5], w.y, hbv.y);
            fma2(acc[6], w.x, hc.x);  fma2(acc[6], w.y, hc.y);
            fma2(acc[7], w.x, hd.x);  fma2(acc[7], w.y, hd.y);
            w = *(const ulonglong2*)(w2r + k);
            fma2(acc[8], w.x, ha.x);  fma2(acc[8], w.y, ha.y);
            fma2(acc[9], w.x, hbv.x); fma2(acc[9], w.y, hbv.y);
            fma2(acc[10], w.x, hc.x); fma2(acc[10], w.y, hc.y);
            fma2(acc[11], w.x, hd.x); fma2(acc[11], w.y, hd.y);
            w = *(const ulonglong2*)(w3r + k);
            fma2(acc[12], w.x, ha.x); fma2(acc[12], w.y, ha.y);
            fma2(acc[13], w.x, hbv.x);fma2(acc[13], w.y, hbv.y);
            fma2(acc[14], w.x, hc.x); fma2(acc[14], w.y, hc.y);
            fma2(acc[15], w.x, hd.x); fma2(acc[15], w.y, hd.y);
        }

        // store partials: per (ks,slot), 4 float4s = gates(i,f,g,o) for j=0..3
        float* rp = sR + (ks * 64 + slot) * RSTR;
        *(float4*)(rp + 0)  = make_float4(psum(acc[0]), psum(acc[4]), psum(acc[8]),  psum(acc[12]));
        *(float4*)(rp + 4)  = make_float4(psum(acc[1]), psum(acc[5]), psum(acc[9]),  psum(acc[13]));
        *(float4*)(rp + 8)  = make_float4(psum(acc[2]), psum(acc[6]), psum(acc[10]), psum(acc[14]));
        *(float4*)(rp + 12) = make_float4(psum(acc[3]), psum(acc[7]), psum(acc[11]), psum(acc[15]));
        __syncthreads();

        // distributed epilogue: threads 0..255 finish one (b,u) each
        if (epi) {
            float4 s = *(const float4*)(sR + (0 * 64 + eslot) * RSTR + ej * 4);
            float gi = s.x, gf = s.y, gc = s.z, go = s.w;
#pragma unroll
            for (int kk = 1; kk < 8; kk++) {
                const float4 sk = *(const float4*)(sR + (kk * 64 + eslot) * RSTR + ej * 4);
                gi += sk.x; gf += sk.y; gc += sk.z; go += sk.w;
            }
            gi += p0; gf += p1; gc += p2; go += p3;
            const float si = __fdividef(1.f, 1.f + __expf(-gi));
            const float sf = __fdividef(1.f, 1.f + __expf(-gf));
            const float so = __fdividef(1.f, 1.f + __expf(-go));
            const float tg = 2.f * __fdividef(1.f, 1.f + __expf(-2.f * gc)) - 1.f;
            c = sf * c + si * tg;
            const float tc = 2.f * __fdividef(1.f, 1.f + __expf(-2.f * c)) - 1.f;
            const float hn = so * tc;
            hlast = hn;
            xout[((size_t)gb * Tn + t) * HIDn + gu] = hn;
            g_h[(t + 1) & 1][gb * HIDn + gu] = hn;
        }
        group_sync(bb);
    }

    if (epi) {
        hout[gb * HIDn + gu] = hlast;
        cout[gb * HIDn + gu] = c;
    }
}

// =============================================================================
extern "C" void kernel_launch(void* const* d_in, const int* in_sizes, int n_in,
                              void* d_out, int out_size)
{
    const float* x      = (const float*)d_in[0];
    const float* states = (const float*)d_in[1];
    const float* W_enc  = (const float*)d_in[2];
    const float* ln_g   = (const float*)d_in[3];
    const float* ln_b   = (const float*)d_in[4];
    const float* Wih1   = (const float*)d_in[5];
    const float* Whh1   = (const float*)d_in[6];
    const float* bih1   = (const float*)d_in[7];
    const float* bhh1   = (const float*)d_in[8];
    const float* Wih2   = (const float*)d_in[9];
    const float* Whh2   = (const float*)d_in[10];
    const float* bih2   = (const float*)d_in[11];
    const float* bhh2   = (const float*)d_in[12];
    const float* Wlin   = (const float*)d_in[13];
    const float* blin   = (const float*)d_in[14];
    const float* W_dec  = (const float*)d_in[15];

    float* out     = (float*)d_out;
    float* dstates = out + (size_t)Bn * FRAMEn * Tn;   // [4,B,HID]

    float *encoded, *buf, *pre, *x1;
    cudaGetSymbolAddress((void**)&encoded, g_encoded);
    cudaGetSymbolAddress((void**)&buf,     g_buf);
    cudaGetSymbolAddress((void**)&pre,     g_pre);
    cudaGetSymbolAddress((void**)&x1,      g_x1);

    static int smem_set = 0;
    const int LSTM_SMEM = (80 * WROW + 8 * 64 * RSTR) * 4;   // 206,080 B
    if (!smem_set) {
        cudaFuncSetAttribute(lstm_kernel,
                             cudaFuncAttributeMaxDynamicSharedMemorySize, LSTM_SMEM);
        smem_set = 1;
    }

    const int BH = Bn * HIDn;   // 32768

    // 1) encoder
    gemm_k<1, 0><<<dim3(ENCn / 128, Tn / 128, Bn), 256>>>(
        x, W_enc, encoded, 0, 0, 0,
        Tn, ENCn, FRAMEn, (size_t)FRAMEn * Tn, 0, (size_t)Tn * ENCn);

    // 2) layernorm
    ln_kernel<<<(Bn * Tn) / 8, 256>>>(encoded, buf, ln_g, ln_b);

    // 3) pre1
    gemm_k<0, 1><<<dim3(G4n / 128, (Bn * Tn) / 128, 1), 256>>>(
        buf, Wih1, pre, 0, bih1, bhh1,
        Bn * Tn, G4n, ENCn, 0, 0, 0);

    // 4) LSTM layer 1
    lstm_kernel<<<NBLK, 512, LSTM_SMEM>>>(
        pre, Whh1, states + 0 * BH, states + 1 * BH,
        x1, dstates + 0 * BH, dstates + 1 * BH);

    // 5) pre2
    gemm_k<0, 1><<<dim3(G4n / 128, (Bn * Tn) / 128, 1), 256>>>(
        x1, Wih2, pre, 0, bih2, bhh2,
        Bn * Tn, G4n, HIDn, 0, 0, 0);

    // 6) LSTM layer 2
    lstm_kernel<<<NBLK, 512, LSTM_SMEM>>>(
        pre, Whh2, states + 2 * BH, states + 3 * BH,
        x1, dstates + 2 * BH, dstates + 3 * BH);

    // 7) est = sigmoid(x2 @ Wlin^T + blin) * encoded
    gemm_k<0, 2><<<dim3(ENCn / 128, (Bn * Tn) / 128, 1), 256>>>(
        x1, Wlin, buf, encoded, blin, 0,
        Bn * Tn, ENCn, HIDn, 0, 0, 0);

    // 8) decoder
    gemm_k<0, 0><<<dim3(Tn / 128, FRAMEn / 128, Bn), 256>>>(
        W_dec, buf, out, 0, 0, 0,
        FRAMEn, Tn, ENCn, 0, (size_t)Tn * ENCn, (size_t)FRAMEn * Tn);
}

// round 10
// speedup vs baseline: 8.5069x; 1.1117x over previous
#include <cuda_runtime.h>
#include <cuda_bf16.h>
#include <cstdint>
#include <math.h>

#define Bn     64
#define Tn     1024
#define FRAMEn 512
#define ENCn   256
#define HIDn   512
#define G4n    2048
#define NBLK   128
#define GSIZE  32
#define WROW   516
#define RSTR   20
#define APAD   40      // smem row stride (bf16) for mma tiles: 20 words -> conflict-free

// ---------------- static device scratch (no cudaMalloc allowed) --------------
__device__ float g_encoded[(size_t)Bn * Tn * ENCn];
__device__ float g_buf[(size_t)Bn * Tn * ENCn];
__device__ float g_pre[(size_t)Bn * Tn * G4n];
__device__ float g_x1[(size_t)Bn * Tn * HIDn];
__device__ float g_h[2][Bn * HIDn];
__device__ unsigned g_cnt[4];
__device__ unsigned g_gen[4];
__device__ __nv_bfloat16 g_ah[(size_t)Bn * Tn * HIDn];   // activation hi
__device__ __nv_bfloat16 g_al[(size_t)Bn * Tn * HIDn];   // activation lo
__device__ __nv_bfloat16 g_wh[(size_t)G4n * HIDn];       // weight hi
__device__ __nv_bfloat16 g_wl[(size_t)G4n * HIDn];       // weight lo

// ---------------- acquire/release barrier primitives -------------------------
__device__ __forceinline__ unsigned atom_add_release(unsigned* p, unsigned v) {
    unsigned old;
    asm volatile("atom.add.release.gpu.global.u32 %0, [%1], %2;"
                 : "=r"(old) : "l"(p), "r"(v) : "memory");
    return old;
}
__device__ __forceinline__ unsigned ld_acquire(const unsigned* p) {
    unsigned v;
    asm volatile("ld.acquire.gpu.global.u32 %0, [%1];" : "=r"(v) : "l"(p) : "memory");
    return v;
}
__device__ __forceinline__ void st_relaxed(unsigned* p, unsigned v) {
    asm volatile("st.relaxed.gpu.global.u32 [%0], %1;" :: "l"(p), "r"(v) : "memory");
}
__device__ __forceinline__ void red_add_release(unsigned* p, unsigned v) {
    asm volatile("red.add.release.gpu.global.u32 [%0], %1;" :: "l"(p), "r"(v) : "memory");
}
__device__ __forceinline__ void group_sync(int g) {
    __syncthreads();
    if (threadIdx.x == 0) {
        const unsigned gen = ld_acquire(&g_gen[g]);
        if (atom_add_release(&g_cnt[g], 1u) == GSIZE - 1) {
            st_relaxed(&g_cnt[g], 0u);
            red_add_release(&g_gen[g], 1u);
        } else {
            while (ld_acquire(&g_gen[g]) == gen) { }
        }
    }
    __syncthreads();
}

// ---------------- packed f32x2 helpers ----------------------------------------
__device__ __forceinline__ void fma2(unsigned long long& d,
                                     unsigned long long a, unsigned long long b) {
    asm("fma.rn.f32x2 %0, %1, %2, %0;" : "+l"(d) : "l"(a), "l"(b));
}
__device__ __forceinline__ unsigned long long bcast2(float v) {
    unsigned long long d;
    asm("mov.b64 %0, {%1, %1};" : "=l"(d) : "r"(__float_as_uint(v)));
    return d;
}
__device__ __forceinline__ float lo2(unsigned long long v) {
    return __uint_as_float((unsigned)v);
}
__device__ __forceinline__ float hi2(unsigned long long v) {
    return __uint_as_float((unsigned)(v >> 32));
}
__device__ __forceinline__ float psum(unsigned long long v) { return lo2(v) + hi2(v); }

// ---------------- mma.sync helpers ---------------------------------------------
__device__ __forceinline__ uint32_t smem_u32(const void* p) {
    uint32_t a;
    asm("{ .reg .u64 t; cvta.to.shared.u64 t, %1; cvt.u32.u64 %0, t; }" : "=r"(a) : "l"(p));
    return a;
}
__device__ __forceinline__ void ldmx4(uint32_t& r0, uint32_t& r1, uint32_t& r2,
                                      uint32_t& r3, uint32_t addr) {
    asm volatile("ldmatrix.sync.aligned.m8n8.x4.shared.b16 {%0,%1,%2,%3}, [%4];"
                 : "=r"(r0), "=r"(r1), "=r"(r2), "=r"(r3) : "r"(addr));
}
__device__ __forceinline__ void mma16816(float* d, const uint32_t* a,
                                         const uint32_t* b) {
    asm volatile(
        "mma.sync.aligned.m16n8k16.row.col.f32.bf16.bf16.f32 "
        "{%0,%1,%2,%3}, {%4,%5,%6,%7}, {%8,%9}, {%0,%1,%2,%3};"
        : "+f"(d[0]), "+f"(d[1]), "+f"(d[2]), "+f"(d[3])
        : "r"(a[0]), "r"(a[1]), "r"(a[2]), "r"(a[3]), "r"(b[0]), "r"(b[1]));
}

// =============================================================================
// split-bf16 HMMA GEMM: C[M,N] = (Ah+Al)[M,K] @ (Bh+Bl)[N,K]^T + b1[n]+b2[n]
// 3 passes (hh, hl, lh). Tile 128x128, BK=32, 256 threads (8 warps, 64x32 each).
// =============================================================================
__global__ void __launch_bounds__(256) gemm_mma(
    const __nv_bfloat16* __restrict__ Ah, const __nv_bfloat16* __restrict__ Al,
    const __nv_bfloat16* __restrict__ Bh, const __nv_bfloat16* __restrict__ Bl,
    float* __restrict__ C, const float* __restrict__ b1, const float* __restrict__ b2,
    int M, int N, int K)
{
    __shared__ __nv_bfloat16 sAh[128 * APAD], sAl[128 * APAD];
    __shared__ __nv_bfloat16 sBh[128 * APAD], sBl[128 * APAD];

    const int tid  = threadIdx.x;
    const int wid  = tid >> 5, lane = tid & 31;
    const int wm   = wid >> 2;            // 0..1  (m block of 64)
    const int wn   = wid & 3;             // 0..3  (n block of 32)
    const int n0   = blockIdx.x * 128;
    const size_t m0 = (size_t)blockIdx.y * 128;

    const uint32_t bAh = smem_u32(sAh), bAl = smem_u32(sAl);
    const uint32_t bBh = smem_u32(sBh), bBl = smem_u32(sBl);

    // ldmatrix lane addressing
    const int lq = lane >> 3, lr = lane & 7;
    // A: row = rA + (lq&1)*8 + lr ; kcol = (lq>>1)*8
    const int aRow = (lq & 1) * 8 + lr;
    const int aK   = (lq >> 1) * 8;
    // B: row = rB + (lq>>1)*8 + lr ; kcol = (lq&1)*8
    const int bRow = (lq >> 1) * 8 + lr;
    const int bK   = (lq & 1) * 8;

    float acc[4][4][4];
#pragma unroll
    for (int i = 0; i < 4; i++)
#pragma unroll
        for (int j = 0; j < 4; j++)
#pragma unroll
            for (int k = 0; k < 4; k++) acc[i][j][k] = 0.f;

    const int nch = K >> 5;
    for (int ch = 0; ch < nch; ch++) {
        const int k0 = ch << 5;
        // load 128x32 chunks of all 4 operand tiles
#pragma unroll
        for (int j = 0; j < 2; j++) {
            const int idx = tid + j * 256;
            const int r = idx >> 2, s = idx & 3;
            const size_t ga = (m0 + r) * K + k0 + s * 8;
            const size_t gb = (size_t)(n0 + r) * K + k0 + s * 8;
            *(uint4*)(sAh + r * APAD + s * 8) = *(const uint4*)(Ah + ga);
            *(uint4*)(sAl + r * APAD + s * 8) = *(const uint4*)(Al + ga);
            *(uint4*)(sBh + r * APAD + s * 8) = *(const uint4*)(Bh + gb);
            *(uint4*)(sBl + r * APAD + s * 8) = *(const uint4*)(Bl + gb);
        }
        __syncthreads();

#pragma unroll
        for (int ks = 0; ks < 2; ks++) {
            uint32_t ah[4][4], al[4][4], bh[4][2], bl[4][2];
#pragma unroll
            for (int mt = 0; mt < 4; mt++) {
                const uint32_t off =
                    (uint32_t)((wm * 64 + mt * 16 + aRow) * APAD + ks * 16 + aK) * 2;
                ldmx4(ah[mt][0], ah[mt][1], ah[mt][2], ah[mt][3], bAh + off);
                ldmx4(al[mt][0], al[mt][1], al[mt][2], al[mt][3], bAl + off);
            }
#pragma unroll
            for (int p = 0; p < 2; p++) {   // each x4 covers 16 n
                const uint32_t off =
                    (uint32_t)((wn * 32 + p * 16 + bRow) * APAD + ks * 16 + bK) * 2;
                uint32_t r0, r1, r2, r3;
                ldmx4(r0, r1, r2, r3, bBh + off);
                bh[p * 2][0] = r0; bh[p * 2][1] = r1;
                bh[p * 2 + 1][0] = r2; bh[p * 2 + 1][1] = r3;
                ldmx4(r0, r1, r2, r3, bBl + off);
                bl[p * 2][0] = r0; bl[p * 2][1] = r1;
                bl[p * 2 + 1][0] = r2; bl[p * 2 + 1][1] = r3;
            }
#pragma unroll
            for (int mt = 0; mt < 4; mt++)
#pragma unroll
                for (int nt = 0; nt < 4; nt++) {
                    mma16816(acc[mt][nt], ah[mt], bh[nt]);
                    mma16816(acc[mt][nt], ah[mt], bl[nt]);
                    mma16816(acc[mt][nt], al[mt], bh[nt]);
                }
        }
        __syncthreads();
    }

    // epilogue: bias + direct stores (C frag: rows g,g+8; cols (lane&3)*2,+1)
    const int g = lane >> 2;
    const int cl = (lane & 3) * 2;
#pragma unroll
    for (int nt = 0; nt < 4; nt++) {
        const int n = n0 + wn * 32 + nt * 8 + cl;
        const float bx = b1[n] + b2[n];
        const float by = b1[n + 1] + b2[n + 1];
#pragma unroll
        for (int mt = 0; mt < 4; mt++) {
            const size_t r0 = m0 + wm * 64 + mt * 16 + g;
            float2 v0 = make_float2(acc[mt][nt][0] + bx, acc[mt][nt][1] + by);
            float2 v1 = make_float2(acc[mt][nt][2] + bx, acc[mt][nt][3] + by);
            *(float2*)(C + r0 * N + n)       = v0;
            *(float2*)(C + (r0 + 8) * N + n) = v1;
        }
    }
}

// ---------------- fp32 -> (hi, lo) bf16 splitter ------------------------------
__global__ void __launch_bounds__(256) split_kernel(
    const float* __restrict__ x, __nv_bfloat16* __restrict__ hi,
    __nv_bfloat16* __restrict__ lo, int n4)
{
    const int i = blockIdx.x * 256 + threadIdx.x;
    if (i >= n4) return;
    const float4 v = ((const float4*)x)[i];
    __nv_bfloat162 h0 = __floats2bfloat162_rn(v.x, v.y);
    __nv_bfloat162 h1 = __floats2bfloat162_rn(v.z, v.w);
    __nv_bfloat162 l0 = __floats2bfloat162_rn(v.x - __bfloat162float(h0.x),
                                              v.y - __bfloat162float(h0.y));
    __nv_bfloat162 l1 = __floats2bfloat162_rn(v.z - __bfloat162float(h1.x),
                                              v.w - __bfloat162float(h1.y));
    ((__nv_bfloat162*)hi)[i * 2]     = h0;
    ((__nv_bfloat162*)hi)[i * 2 + 1] = h1;
    ((__nv_bfloat162*)lo)[i * 2]     = l0;
    ((__nv_bfloat162*)lo)[i * 2 + 1] = l1;
}

// =============================================================================
// SIMT fp32 GEMM (f32x2 accumulators, double-buffered) for enc/mask/dec.
// =============================================================================
template <int TRANS_A, int EPI>
__global__ void __launch_bounds__(256, 2) gemm_k(
    const float* __restrict__ A, const float* __restrict__ Bm,
    float* __restrict__ C, const float* __restrict__ E,
    const float* __restrict__ bias1, const float* __restrict__ bias2,
    int M, int N, int K, size_t sA, size_t sB, size_t sC)
{
    __shared__ float As[2][8 * 128];
    __shared__ float Bs[2][8 * 128];

    const int tid = threadIdx.x;
    const size_t z = blockIdx.z;
    const float* Ab = A + z * sA;
    const float* Bb = Bm + z * sB;
    float*       Cb = C + z * sC;
    const float* Eb = (EPI == 2) ? (E + z * sC) : (const float*)0;

    const int n0 = blockIdx.x * 128;
    const int m0 = blockIdx.y * 128;
    const int tx = tid & 15;
    const int ty = tid >> 4;
    const int row  = tid >> 1;
    const int half = tid & 1;
    const int kr   = tid >> 5;
    const int mc   = tid & 31;

    unsigned long long acc2[4][8];
#pragma unroll
    for (int ip = 0; ip < 4; ip++)
#pragma unroll
        for (int j = 0; j < 8; j++) acc2[ip][j] = 0ull;

    float4 pa, pb;
    if (TRANS_A) pa = *(const float4*)(Ab + (size_t)kr * M + m0 + mc * 4);
    else         pa = *(const float4*)(Ab + (size_t)(m0 + row) * K + half * 4);
    pb = *(const float4*)(Bb + (size_t)(n0 + row) * K + half * 4);

    if (TRANS_A) {
        *(float4*)&As[0][kr * 128 + mc * 4] = pa;
    } else {
        As[0][(half * 4 + 0) * 128 + row] = pa.x;
        As[0][(half * 4 + 1) * 128 + row] = pa.y;
        As[0][(half * 4 + 2) * 128 + row] = pa.z;
        As[0][(half * 4 + 3) * 128 + row] = pa.w;
    }
    Bs[0][(half * 4 + 0) * 128 + row] = pb.x;
    Bs[0][(half * 4 + 1) * 128 + row] = pb.y;
    Bs[0][(half * 4 + 2) * 128 + row] = pb.z;
    Bs[0][(half * 4 + 3) * 128 + row] = pb.w;
    __syncthreads();

    int buf = 0;
    for (int k0 = 0; k0 < K; k0 += 8) {
        const bool more = (k0 + 8 < K);
        if (more) {
            if (TRANS_A) pa = *(const float4*)(Ab + (size_t)(k0 + 8 + kr) * M + m0 + mc * 4);
            else         pa = *(const float4*)(Ab + (size_t)(m0 + row) * K + k0 + 8 + half * 4);
            pb = *(const float4*)(Bb + (size_t)(n0 + row) * K + k0 + 8 + half * 4);
        }
#pragma unroll
        for (int kk = 0; kk < 8; kk++) {
            ulonglong2 aA = *(const ulonglong2*)&As[buf][kk * 128 + ty * 8];
            ulonglong2 aB = *(const ulonglong2*)&As[buf][kk * 128 + ty * 8 + 4];
            float bv[8];
            *(float4*)(bv)     = *(const float4*)&Bs[buf][kk * 128 + tx * 8];
            *(float4*)(bv + 4) = *(const float4*)&Bs[buf][kk * 128 + tx * 8 + 4];
#pragma unroll
            for (int j = 0; j < 8; j++) {
                const unsigned long long bj = bcast2(bv[j]);
                fma2(acc2[0][j], aA.x, bj);
                fma2(acc2[1][j], aA.y, bj);
                fma2(acc2[2][j], aB.x, bj);
                fma2(acc2[3][j], aB.y, bj);
            }
        }
        if (more) {
            const int nb = buf ^ 1;
            if (TRANS_A) {
                *(float4*)&As[nb][kr * 128 + mc * 4] = pa;
            } else {
                As[nb][(half * 4 + 0) * 128 + row] = pa.x;
                As[nb][(half * 4 + 1) * 128 + row] = pa.y;
                As[nb][(half * 4 + 2) * 128 + row] = pa.z;
                As[nb][(half * 4 + 3) * 128 + row] = pa.w;
            }
            Bs[nb][(half * 4 + 0) * 128 + row] = pb.x;
            Bs[nb][(half * 4 + 1) * 128 + row] = pb.y;
            Bs[nb][(half * 4 + 2) * 128 + row] = pb.z;
            Bs[nb][(half * 4 + 3) * 128 + row] = pb.w;
            __syncthreads();
            buf = nb;
        }
    }

#pragma unroll
    for (int ip = 0; ip < 4; ip++) {
#pragma unroll
        for (int hf = 0; hf < 2; hf++) {
            const int i = ip * 2 + hf;
            const int m = m0 + ty * 8 + i;
            float* crow = Cb + (size_t)m * N;
#pragma unroll
            for (int j = 0; j < 8; j += 4) {
                const int n = n0 + tx * 8 + j;
                float4 v;
                v.x = hf ? hi2(acc2[ip][j])     : lo2(acc2[ip][j]);
                v.y = hf ? hi2(acc2[ip][j + 1]) : lo2(acc2[ip][j + 1]);
                v.z = hf ? hi2(acc2[ip][j + 2]) : lo2(acc2[ip][j + 2]);
                v.w = hf ? hi2(acc2[ip][j + 3]) : lo2(acc2[ip][j + 3]);
                if (EPI == 1) {
                    v.x += bias1[n]     + bias2[n];
                    v.y += bias1[n + 1] + bias2[n + 1];
                    v.z += bias1[n + 2] + bias2[n + 2];
                    v.w += bias1[n + 3] + bias2[n + 3];
                } else if (EPI == 2) {
                    float4 e = *(const float4*)(Eb + (size_t)m * N + n);
                    v.x = e.x / (1.f + expf(-(v.x + bias1[n])));
                    v.y = e.y / (1.f + expf(-(v.y + bias1[n + 1])));
                    v.z = e.z / (1.f + expf(-(v.z + bias1[n + 2])));
                    v.w = e.w / (1.f + expf(-(v.w + bias1[n + 3])));
                }
                *(float4*)(crow + n) = v;
            }
        }
    }
}

// ---------------- layernorm -> bf16 hi/lo (feeds pre1 mma GEMM) ---------------
__global__ void __launch_bounds__(256) ln_kernel(
    const float* __restrict__ in, __nv_bfloat16* __restrict__ hi,
    __nv_bfloat16* __restrict__ lo,
    const float* __restrict__ gam, const float* __restrict__ bet)
{
    const int row  = blockIdx.x * 8 + (threadIdx.x >> 5);
    const int lane = threadIdx.x & 31;
    const float* r = in + (size_t)row * ENCn + lane * 8;
    float4 a  = *(const float4*)r;
    float4 b4 = *(const float4*)(r + 4);
    float s  = a.x + a.y + a.z + a.w + b4.x + b4.y + b4.z + b4.w;
    float sq = a.x*a.x + a.y*a.y + a.z*a.z + a.w*a.w
             + b4.x*b4.x + b4.y*b4.y + b4.z*b4.z + b4.w*b4.w;
#pragma unroll
    for (int o = 16; o; o >>= 1) {
        s  += __shfl_xor_sync(0xFFFFFFFFu, s,  o);
        sq += __shfl_xor_sync(0xFFFFFFFFu, sq, o);
    }
    const float mu   = s * (1.f / 256.f);
    const float var  = sq * (1.f / 256.f) - mu * mu;
    const float rstd = rsqrtf(var + 1e-5f);

    const float* gg = gam + lane * 8;
    const float* bb = bet + lane * 8;
    float4 ga = *(const float4*)gg,  gb  = *(const float4*)(gg + 4);
    float4 ba = *(const float4*)bb,  bbv = *(const float4*)(bb + 4);
    float o8[8];
    o8[0] = (a.x  - mu) * rstd * ga.x + ba.x;
    o8[1] = (a.y  - mu) * rstd * ga.y + ba.y;
    o8[2] = (a.z  - mu) * rstd * ga.z + ba.z;
    o8[3] = (a.w  - mu) * rstd * ga.w + ba.w;
    o8[4] = (b4.x - mu) * rstd * gb.x + bbv.x;
    o8[5] = (b4.y - mu) * rstd * gb.y + bbv.y;
    o8[6] = (b4.z - mu) * rstd * gb.z + bbv.z;
    o8[7] = (b4.w - mu) * rstd * gb.w + bbv.w;

    const size_t base = (size_t)row * ENCn + lane * 8;
#pragma unroll
    for (int k = 0; k < 8; k += 2) {
        __nv_bfloat162 h = __floats2bfloat162_rn(o8[k], o8[k + 1]);
        __nv_bfloat162 l = __floats2bfloat162_rn(o8[k]     - __bfloat162float(h.x),
                                                 o8[k + 1] - __bfloat162float(h.y));
        *(__nv_bfloat162*)(hi + base + k) = h;
        *(__nv_bfloat162*)(lo + base + k) = l;
    }
}

// ---------------- persistent LSTM layer (512 threads, 8-way k) ---------------
__global__ void __launch_bounds__(512) lstm_kernel(
    const float* __restrict__ pre, const float* __restrict__ Whh,
    const float* __restrict__ h0,  const float* __restrict__ c0,
    float* __restrict__ xout, __nv_bfloat16* __restrict__ bfh,
    __nv_bfloat16* __restrict__ bfl,
    float* __restrict__ hout, float* __restrict__ cout)
{
    extern __shared__ float sm[];
    float* sW = sm;
    float* sH = sm + 64 * WROW;
    float* sR = sm + 80 * WROW;

    const int tid  = threadIdx.x, cta = blockIdx.x;
    const int ub   = cta & 31, bb = cta >> 5;
    const int warp = tid >> 5, lane = tid & 31;
    const int ks    = warp & 7;
    const int bq_hi = warp >> 3;
    const int ul    = lane & 15;
    const int bq_lo = lane >> 4;
    const int bq    = bq_hi * 2 + bq_lo;
    const int slot  = bq * 16 + ul;
    const int e_u   = tid & 15;
    const int e_b   = (tid >> 4) & 15;
    const int eslot = (e_b >> 2) * 16 + e_u;
    const int ej    = e_b & 3;
    const int gb    = bb * 16 + e_b;
    const int gu    = ub * 16 + e_u;
    const bool epi  = (tid < 256);

    for (int i = tid; i < 64 * 128; i += 512) {
        const int r  = i >> 7;
        const int k4 = i & 127;
        const int g  = r >> 4;
        const int uu = ub * 16 + (r & 15);
        *(float4*)(sW + r * WROW + k4 * 4) =
            *(const float4*)(Whh + ((size_t)(g * HIDn + uu)) * HIDn + k4 * 4);
    }
    if (epi) g_h[0][cta * 256 + tid] = h0[cta * 256 + tid];
    float c = 0.f, hlast = 0.f;
    if (epi) c = c0[gb * HIDn + gu];
    group_sync(bb);

    const float* w0r = sW + (0 * 16 + ul) * WROW + ks * 64;
    const float* w1r = sW + (1 * 16 + ul) * WROW + ks * 64;
    const float* w2r = sW + (2 * 16 + ul) * WROW + ks * 64;
    const float* w3r = sW + (3 * 16 + ul) * WROW + ks * 64;
    const float* hb0 = sH + (bq * 4 + 0) * WROW + ks * 64;
    const float* hb1 = sH + (bq * 4 + 1) * WROW + ks * 64;
    const float* hb2 = sH + (bq * 4 + 2) * WROW + ks * 64;
    const float* hb3 = sH + (bq * 4 + 3) * WROW + ks * 64;

    for (int t = 0; t < Tn; t++) {
        const float* hr = g_h[t & 1] + (size_t)bb * 16 * HIDn;
        for (int i = tid; i < 16 * 128; i += 512) {
            const int rr = i >> 7, k4 = i & 127;
            *(float4*)(sH + rr * WROW + k4 * 4) =
                *(const float4*)(hr + (size_t)rr * HIDn + k4 * 4);
        }
        float p0 = 0.f, p1 = 0.f, p2 = 0.f, p3 = 0.f;
        if (epi) {
            const float* pb = pre + ((size_t)gb * Tn + t) * G4n + gu;
            p0 = pb[0]; p1 = pb[512]; p2 = pb[1024]; p3 = pb[1536];
        }
        __syncthreads();

        unsigned long long acc[16];
#pragma unroll
        for (int i = 0; i < 16; i++) acc[i] = 0ull;

#pragma unroll 8
        for (int q = 0; q < 16; q++) {
            const int k = q * 4;
            const ulonglong2 ha  = *(const ulonglong2*)(hb0 + k);
            const ulonglong2 hbv = *(const ulonglong2*)(hb1 + k);
            const ulonglong2 hc  = *(const ulonglong2*)(hb2 + k);
            const ulonglong2 hd  = *(const ulonglong2*)(hb3 + k);
            ulonglong2 w;
            w = *(const ulonglong2*)(w0r + k);
            fma2(acc[0], w.x, ha.x);  fma2(acc[0], w.y, ha.y);
            fma2(acc[1], w.x, hbv.x); fma2(acc[1], w.y, hbv.y);
            fma2(acc[2], w.x, hc.x);  fma2(acc[2], w.y, hc.y);
            fma2(acc[3], w.x, hd.x);  fma2(acc[3], w.y, hd.y);
            w = *(const ulonglong2*)(w1r + k);
            fma2(acc[4], w.x, ha.x);  fma2(acc[4], w.y, ha.y);
            fma2(acc[5], w.x, hbv.x); fma2(acc[5], w.y, hbv.y);
            fma2(acc[6], w.x, hc.x);  fma2(acc[6], w.y, hc.y);
            fma2(acc[7], w.x, hd.x);  fma2(acc[7], w.y, hd.y);
            w = *(const ulonglong2*)(w2r + k);
            fma2(acc[8], w.x, ha.x);  fma2(acc[8], w.y, ha.y);
            fma2(acc[9], w.x, hbv.x); fma2(acc[9], w.y, hbv.y);
            fma2(acc[10], w.x, hc.x); fma2(acc[10], w.y, hc.y);
            fma2(acc[11], w.x, hd.x); fma2(acc[11], w.y, hd.y);
            w = *(const ulonglong2*)(w3r + k);
            fma2(acc[12], w.x, ha.x); fma2(acc[12], w.y, ha.y);
            fma2(acc[13], w.x, hbv.x);fma2(acc[13], w.y, hbv.y);
            fma2(acc[14], w.x, hc.x); fma2(acc[14], w.y, hc.y);
            fma2(acc[15], w.x, hd.x); fma2(acc[15], w.y, hd.y);
        }

        float* rp = sR + (ks * 64 + slot) * RSTR;
        *(float4*)(rp + 0)  = make_float4(psum(acc[0]), psum(acc[4]), psum(acc[8]),  psum(acc[12]));
        *(float4*)(rp + 4)  = make_float4(psum(acc[1]), psum(acc[5]), psum(acc[9]),  psum(acc[13]));
        *(float4*)(rp + 8)  = make_float4(psum(acc[2]), psum(acc[6]), psum(acc[10]), psum(acc[14]));
        *(float4*)(rp + 12) = make_float4(psum(acc[3]), psum(acc[7]), psum(acc[11]), psum(acc[15]));
        __syncthreads();

        if (epi) {
            float4 s = *(const float4*)(sR + (0 * 64 + eslot) * RSTR + ej * 4);
            float gi = s.x, gf = s.y, gc = s.z, go = s.w;
#pragma unroll
            for (int kk = 1; kk < 8; kk++) {
                const float4 sk = *(const float4*)(sR + (kk * 64 + eslot) * RSTR + ej * 4);
                gi += sk.x; gf += sk.y; gc += sk.z; go += sk.w;
            }
            gi += p0; gf += p1; gc += p2; go += p3;
            const float si = __fdividef(1.f, 1.f + __expf(-gi));
            const float sf = __fdividef(1.f, 1.f + __expf(-gf));
            const float so = __fdividef(1.f, 1.f + __expf(-go));
            const float tg = 2.f * __fdividef(1.f, 1.f + __expf(-2.f * gc)) - 1.f;
            c = sf * c + si * tg;
            const float tc = 2.f * __fdividef(1.f, 1.f + __expf(-2.f * c)) - 1.f;
            const float hn = so * tc;
            hlast = hn;
            const size_t xo = ((size_t)gb * Tn + t) * HIDn + gu;
            if (bfh) {   // layer 1: emit bf16 hi/lo for the mma pre2 GEMM
                __nv_bfloat16 hh = __float2bfloat16(hn);
                bfh[xo] = hh;
                bfl[xo] = __float2bfloat16(hn - __bfloat162float(hh));
            } else {
                xout[xo] = hn;
            }
            g_h[(t + 1) & 1][gb * HIDn + gu] = hn;
        }
        group_sync(bb);
    }

    if (epi) {
        hout[gb * HIDn + gu] = hlast;
        cout[gb * HIDn + gu] = c;
    }
}

// =============================================================================
extern "C" void kernel_launch(void* const* d_in, const int* in_sizes, int n_in,
                              void* d_out, int out_size)
{
    const float* x      = (const float*)d_in[0];
    const float* states = (const float*)d_in[1];
    const float* W_enc  = (const float*)d_in[2];
    const float* ln_g   = (const float*)d_in[3];
    const float* ln_b   = (const float*)d_in[4];
    const float* Wih1   = (const float*)d_in[5];
    const float* Whh1   = (const float*)d_in[6];
    const float* bih1   = (const float*)d_in[7];
    const float* bhh1   = (const float*)d_in[8];
    const float* Wih2   = (const float*)d_in[9];
    const float* Whh2   = (const float*)d_in[10];
    const float* bih2   = (const float*)d_in[11];
    const float* bhh2   = (const float*)d_in[12];
    const float* Wlin   = (const float*)d_in[13];
    const float* blin   = (const float*)d_in[14];
    const float* W_dec  = (const float*)d_in[15];

    float* out     = (float*)d_out;
    float* dstates = out + (size_t)Bn * FRAMEn * Tn;

    float *encoded, *buf, *pre, *x1;
    __nv_bfloat16 *ah, *al, *wh, *wl;
    cudaGetSymbolAddress((void**)&encoded, g_encoded);
    cudaGetSymbolAddress((void**)&buf,     g_buf);
    cudaGetSymbolAddress((void**)&pre,     g_pre);
    cudaGetSymbolAddress((void**)&x1,      g_x1);
    cudaGetSymbolAddress((void**)&ah,      g_ah);
    cudaGetSymbolAddress((void**)&al,      g_al);
    cudaGetSymbolAddress((void**)&wh,      g_wh);
    cudaGetSymbolAddress((void**)&wl,      g_wl);

    static int attr_set = 0;
    const int LSTM_SMEM = (80 * WROW + 8 * 64 * RSTR) * 4;   // 206,080 B
    if (!attr_set) {
        cudaFuncSetAttribute(lstm_kernel,
                             cudaFuncAttributeMaxDynamicSharedMemorySize, LSTM_SMEM);
        attr_set = 1;
    }

    const int BH = Bn * HIDn;

    // 1) encoder (fp32 SIMT)
    gemm_k<1, 0><<<dim3(ENCn / 128, Tn / 128, Bn), 256>>>(
        x, W_enc, encoded, 0, 0, 0,
        Tn, ENCn, FRAMEn, (size_t)FRAMEn * Tn, 0, (size_t)Tn * ENCn);

    // 2) layernorm -> bf16 hi/lo (A of pre1)
    ln_kernel<<<(Bn * Tn) / 8, 256>>>(encoded, ah, al, ln_g, ln_b);

    // 3) pre1 = enc_norm @ Wih1^T + bih1 + bhh1  (HMMA split-bf16)
    split_kernel<<<(G4n * ENCn / 4 + 255) / 256, 256>>>(Wih1, wh, wl, G4n * ENCn / 4);
    gemm_mma<<<dim3(G4n / 128, (Bn * Tn) / 128), 256>>>(
        ah, al, wh, wl, pre, bih1, bhh1, Bn * Tn, G4n, ENCn);

    // 4) LSTM layer 1 (emits x1 as bf16 hi/lo)
    lstm_kernel<<<NBLK, 512, LSTM_SMEM>>>(
        pre, Whh1, states + 0 * BH, states + 1 * BH,
        x1, ah, al, dstates + 0 * BH, dstates + 1 * BH);

    // 5) pre2 = x1 @ Wih2^T + bih2 + bhh2  (HMMA split-bf16)
    split_kernel<<<(G4n * HIDn / 4 + 255) / 256, 256>>>(Wih2, wh, wl, G4n * HIDn / 4);
    gemm_mma<<<dim3(G4n / 128, (Bn * Tn) / 128), 256>>>(
        ah, al, wh, wl, pre, bih2, bhh2, Bn * Tn, G4n, HIDn);

    // 6) LSTM layer 2 (fp32 x2 -> g_x1)
    lstm_kernel<<<NBLK, 512, LSTM_SMEM>>>(
        pre, Whh2, states + 2 * BH, states + 3 * BH,
        x1, (__nv_bfloat16*)0, (__nv_bfloat16*)0,
        dstates + 2 * BH, dstates + 3 * BH);

    // 7) est = sigmoid(x2 @ Wlin^T + blin) * encoded
    gemm_k<0, 2><<<dim3(ENCn / 128, (Bn * Tn) / 128, 1), 256>>>(
        x1, Wlin, buf, encoded, blin, 0,
        Bn * Tn, ENCn, HIDn, 0, 0, 0);

    // 8) decoder
    gemm_k<0, 0><<<dim3(Tn / 128, FRAMEn / 128, Bn), 256>>>(
        W_dec, buf, out, 0, 0, 0,
        FRAMEn, Tn, ENCn, 0, (size_t)Tn * ENCn, (size_t)FRAMEn * Tn);
}